// round 3
// baseline (speedup 1.0000x reference)
#include <cuda_runtime.h>
#include <cuda_bf16.h>
#include <cstdint>

#define GN 50000
#define GE 1600000
#define FULLMASK 0xFFFFFFFFu

// ---------------- scratch (device globals; no allocation allowed) ----------------
__device__ float g_f128[GN * 128];   // [d | n | c | zeros] per node
__device__ float g_xA[GN * 128];
__device__ float g_tr[GN * 128];     // [t (x@Wl) | r (x@Wr)]
__device__ float g_h[GN * 64];
__device__ float g_mh[GN * 128];     // [mean(h) | h]
__device__ float g_xB[GN * 128];
__device__ float g_ob[GN * 128];
__device__ int   g_cnt[GN];
__device__ int   g_rowptr[GN + 1];
__device__ int   g_cursor[GN];
__device__ int   g_col[GE];
__device__ float g_invdeg[GN];

// ---------------- CSR build ----------------
__global__ void zero_cnt_kernel(int n) {
    int i = blockIdx.x * blockDim.x + threadIdx.x;
    if (i < n) g_cnt[i] = 0;
}

__global__ void count_kernel(const int* __restrict__ dst, int e) {
    int i = blockIdx.x * blockDim.x + threadIdx.x;
    if (i < e) atomicAdd(&g_cnt[dst[i]], 1);
}

// single-block exclusive scan over g_cnt -> g_rowptr, g_cursor, g_invdeg
__global__ void scan_kernel(int n) {
    __shared__ int wsum[32];
    __shared__ int carry_s;
    int tid = threadIdx.x, lane = tid & 31, wid = tid >> 5;
    if (tid == 0) carry_s = 0;
    __syncthreads();
    for (int base = 0; base < n; base += 1024) {
        int i = base + tid;
        int v = (i < n) ? g_cnt[i] : 0;
        int x = v;
        #pragma unroll
        for (int o = 1; o < 32; o <<= 1) {
            int t = __shfl_up_sync(FULLMASK, x, o);
            if (lane >= o) x += t;
        }
        if (lane == 31) wsum[wid] = x;
        __syncthreads();
        if (wid == 0) {
            int y = wsum[lane];
            #pragma unroll
            for (int o = 1; o < 32; o <<= 1) {
                int t = __shfl_up_sync(FULLMASK, y, o);
                if (lane >= o) y += t;
            }
            wsum[lane] = y;
        }
        __syncthreads();
        int incl = x + (wid > 0 ? wsum[wid - 1] : 0);
        int total = wsum[31];
        int carry = carry_s;
        if (i < n) {
            int rp = carry + incl - v;   // exclusive
            g_rowptr[i] = rp;
            g_cursor[i] = rp;
            int d = v > 1 ? v : 1;
            g_invdeg[i] = 1.0f / (float)d;
        }
        __syncthreads();
        if (tid == 0) carry_s = carry + total;
        __syncthreads();
    }
    if (threadIdx.x == 0) g_rowptr[n] = carry_s;
}

__global__ void scatter_kernel(const int* __restrict__ src, const int* __restrict__ dst, int e) {
    int i = blockIdx.x * blockDim.x + threadIdx.x;
    if (i < e) {
        int p = atomicAdd(&g_cursor[dst[i]], 1);
        g_col[p] = src[i];
    }
}

// ---------------- small front features (num 4->42, cat 3->42) ----------------
__global__ void front_small_kernel(const float* __restrict__ num, const float* __restrict__ cat,
                                   const float* __restrict__ Wn, const float* __restrict__ bn,
                                   const float* __restrict__ Wc, const float* __restrict__ bc, int n) {
    int i = blockIdx.x * blockDim.x + threadIdx.x;
    if (i >= n) return;
    float nv0 = num[i * 4 + 0], nv1 = num[i * 4 + 1], nv2 = num[i * 4 + 2], nv3 = num[i * 4 + 3];
    float cv0 = cat[i * 3 + 0], cv1 = cat[i * 3 + 1], cv2 = cat[i * 3 + 2];
    float* f = g_f128 + (size_t)i * 128;
    for (int o = 0; o < 42; o++) {
        float s = bn[o];
        s = fmaf(nv0, Wn[o], s);
        s = fmaf(nv1, Wn[42 + o], s);
        s = fmaf(nv2, Wn[84 + o], s);
        s = fmaf(nv3, Wn[126 + o], s);
        f[32 + o] = s > 0.f ? s : 0.01f * s;
        float s2 = bc[o];
        s2 = fmaf(cv0, Wc[o], s2);
        s2 = fmaf(cv1, Wc[42 + o], s2);
        s2 = fmaf(cv2, Wc[84 + o], s2);
        f[74 + o] = s2 > 0.f ? s2 : 0.01f * s2;
    }
    #pragma unroll
    for (int o = 116; o < 128; o++) f[o] = 0.f;
}

// ---------------- generic GEMM: out[N,C] = act(A[N,K] @ W + bias) ----------------
// W staged in smem, assembled from up to two sources:
//   colcat=1: cols [0,cols0) from W0 (k*cols0+c), cols [cols0,C) from W1
//   colcat=0: rows [0,rows0) from W0 (cols0==C), rows [rows0,rows0+rows1) from W1, zeros above
// Block: 256 threads = 8 warps; warp handles 8 rows; lane handles CPL cols.
// ACT: 0 none, 1 leaky(0.01), 2 relu
template<int CPL, int ACT>
__global__ void __launch_bounds__(256) gemm_kernel(
    const float* __restrict__ A, int lda, int nrows,
    const float* __restrict__ W0, int rows0, int cols0,
    const float* __restrict__ W1, int rows1, int cols1, int colcat,
    const float* __restrict__ bias,
    float* __restrict__ out, int ldo,
    int K, int C)
{
    extern __shared__ float smem[];
    float* Ws = smem;
    float* Bs = smem + K * C;
    int tid = threadIdx.x;
    int total = K * C;
    for (int idx = tid; idx < total; idx += 256) {
        int k = idx / C, c = idx - k * C;
        float v = 0.f;
        if (colcat) {
            v = (c < cols0) ? W0[k * cols0 + c] : W1[k * cols1 + (c - cols0)];
        } else {
            if (k < rows0) v = W0[k * cols0 + c];
            else if (k < rows0 + rows1) v = W1[(k - rows0) * cols1 + c];
        }
        Ws[idx] = v;
    }
    for (int c = tid; c < C; c += 256) Bs[c] = bias ? bias[c] : 0.f;
    __syncthreads();

    const int warp = tid >> 5, lane = tid & 31;
    const int rowbase = blockIdx.x * 64 + warp * 8;
    const int c0 = lane * CPL;
    const float* Ap[8];
    #pragma unroll
    for (int r = 0; r < 8; r++) {
        int rr = rowbase + r;
        if (rr >= nrows) rr = nrows - 1;
        Ap[r] = A + (size_t)rr * lda;
    }
    float acc[8][CPL];
    #pragma unroll
    for (int r = 0; r < 8; r++)
        #pragma unroll
        for (int c = 0; c < CPL; c++) acc[r][c] = 0.f;

    for (int k = 0; k < K; k += 4) {
        if (CPL == 4) {
            float4 w0 = *(const float4*)&Ws[(k + 0) * C + c0];
            float4 w1 = *(const float4*)&Ws[(k + 1) * C + c0];
            float4 w2 = *(const float4*)&Ws[(k + 2) * C + c0];
            float4 w3 = *(const float4*)&Ws[(k + 3) * C + c0];
            #pragma unroll
            for (int r = 0; r < 8; r++) {
                float4 a = *(const float4*)(Ap[r] + k);
                float t0 = acc[r][0], t1 = acc[r][1], t2 = acc[r][2], t3 = acc[r][3];
                t0 = fmaf(a.x, w0.x, t0); t1 = fmaf(a.x, w0.y, t1); t2 = fmaf(a.x, w0.z, t2); t3 = fmaf(a.x, w0.w, t3);
                t0 = fmaf(a.y, w1.x, t0); t1 = fmaf(a.y, w1.y, t1); t2 = fmaf(a.y, w1.z, t2); t3 = fmaf(a.y, w1.w, t3);
                t0 = fmaf(a.z, w2.x, t0); t1 = fmaf(a.z, w2.y, t1); t2 = fmaf(a.z, w2.z, t2); t3 = fmaf(a.z, w2.w, t3);
                t0 = fmaf(a.w, w3.x, t0); t1 = fmaf(a.w, w3.y, t1); t2 = fmaf(a.w, w3.z, t2); t3 = fmaf(a.w, w3.w, t3);
                acc[r][0] = t0; acc[r][1] = t1; acc[r][2] = t2; acc[r][3] = t3;
            }
        } else {
            float w0 = Ws[(k + 0) * C + c0];
            float w1 = Ws[(k + 1) * C + c0];
            float w2 = Ws[(k + 2) * C + c0];
            float w3 = Ws[(k + 3) * C + c0];
            #pragma unroll
            for (int r = 0; r < 8; r++) {
                float4 a = *(const float4*)(Ap[r] + k);
                float t = acc[r][0];
                t = fmaf(a.x, w0, t); t = fmaf(a.y, w1, t);
                t = fmaf(a.z, w2, t); t = fmaf(a.w, w3, t);
                acc[r][0] = t;
            }
        }
    }

    #pragma unroll
    for (int r = 0; r < 8; r++) {
        int rr = rowbase + r;
        if (rr < nrows) {
            #pragma unroll
            for (int c = 0; c < CPL; c++) {
                float v = acc[r][c] + Bs[c0 + c];
                if (ACT == 1) v = v > 0.f ? v : 0.01f * v;
                else if (ACT == 2) v = v > 0.f ? v : 0.f;
                out[(size_t)rr * ldo + c0 + c] = v;
            }
        }
    }
}

// ---------------- aggregation (warp per node, 64 feature cols, 2 per lane) ----------------
// agg_a: h[i] = relu( mean_nbr(t) + bl + r[i] ), t = tr[:,0:64], r = tr[:,64:128]
__global__ void agg_a_kernel(const float* __restrict__ tr, const float* __restrict__ bl,
                             float* __restrict__ h, int n) {
    int w = (blockIdx.x * blockDim.x + threadIdx.x) >> 5;
    if (w >= n) return;
    int lane = threadIdx.x & 31;
    int c = lane * 2;
    int e = g_rowptr[w], end = g_rowptr[w + 1];
    float s0 = 0.f, s1 = 0.f;
    for (; e + 2 <= end; e += 2) {
        int j0 = g_col[e], j1 = g_col[e + 1];
        float2 v0 = *(const float2*)&tr[(size_t)j0 * 128 + c];
        float2 v1 = *(const float2*)&tr[(size_t)j1 * 128 + c];
        s0 += v0.x + v1.x;
        s1 += v0.y + v1.y;
    }
    if (e < end) {
        int j = g_col[e];
        float2 v = *(const float2*)&tr[(size_t)j * 128 + c];
        s0 += v.x; s1 += v.y;
    }
    float id = g_invdeg[w];
    float2 r = *(const float2*)&tr[(size_t)w * 128 + 64 + c];
    float o0 = fmaf(s0, id, bl[c] + r.x);
    float o1 = fmaf(s1, id, bl[c + 1] + r.y);
    o0 = o0 > 0.f ? o0 : 0.f;
    o1 = o1 > 0.f ? o1 : 0.f;
    *(float2*)&h[(size_t)w * 64 + c] = make_float2(o0, o1);
}

// agg_b: mh[i] = [ mean_nbr(h) | h[i] ]
__global__ void agg_b_kernel(const float* __restrict__ h, float* __restrict__ mh, int n) {
    int w = (blockIdx.x * blockDim.x + threadIdx.x) >> 5;
    if (w >= n) return;
    int lane = threadIdx.x & 31;
    int c = lane * 2;
    int e = g_rowptr[w], end = g_rowptr[w + 1];
    float s0 = 0.f, s1 = 0.f;
    for (; e + 2 <= end; e += 2) {
        int j0 = g_col[e], j1 = g_col[e + 1];
        float2 v0 = *(const float2*)&h[(size_t)j0 * 64 + c];
        float2 v1 = *(const float2*)&h[(size_t)j1 * 64 + c];
        s0 += v0.x + v1.x;
        s1 += v0.y + v1.y;
    }
    if (e < end) {
        int j = g_col[e];
        float2 v = *(const float2*)&h[(size_t)j * 64 + c];
        s0 += v.x; s1 += v.y;
    }
    float id = g_invdeg[w];
    float2 hv = *(const float2*)&h[(size_t)w * 64 + c];
    *(float2*)&mh[(size_t)w * 128 + c] = make_float2(s0 * id, s1 * id);
    *(float2*)&mh[(size_t)w * 128 + 64 + c] = hv;
}

// ---------------- final 128->2 projection (warp per node) ----------------
// out[w, :] = ob[w, 0:128] @ W_o2[128, 2] + b. Each lane covers rows lane, lane+32, lane+64, lane+96.
__global__ void out_kernel(const float* __restrict__ ob, const float* __restrict__ W,
                           const float* __restrict__ b, float* __restrict__ out, int n) {
    int w = (blockIdx.x * blockDim.x + threadIdx.x) >> 5;
    if (w >= n) return;
    int lane = threadIdx.x & 31;
    const float* row = ob + (size_t)w * 128;
    float a0 = row[lane];
    float a1 = row[lane + 32];
    float a2 = row[lane + 64];
    float a3 = row[lane + 96];
    float p0 = a0 * W[lane * 2 + 0] + a1 * W[(lane + 32) * 2 + 0]
             + a2 * W[(lane + 64) * 2 + 0] + a3 * W[(lane + 96) * 2 + 0];
    float p1 = a0 * W[lane * 2 + 1] + a1 * W[(lane + 32) * 2 + 1]
             + a2 * W[(lane + 64) * 2 + 1] + a3 * W[(lane + 96) * 2 + 1];
    #pragma unroll
    for (int o = 16; o; o >>= 1) {
        p0 += __shfl_xor_sync(FULLMASK, p0, o);
        p1 += __shfl_xor_sync(FULLMASK, p1, o);
    }
    if (lane == 0) {
        out[(size_t)w * 2 + 0] = p0 + b[0];
        out[(size_t)w * 2 + 1] = p1 + b[1];
    }
}

// ---------------- host launch ----------------
extern "C" void kernel_launch(void* const* d_in, const int* in_sizes, int n_in,
                              void* d_out, int out_size) {
    const float* des    = (const float*)d_in[0];
    const float* num    = (const float*)d_in[2];
    const float* cat    = (const float*)d_in[3];
    const int*   ei     = (const int*)  d_in[4];
    const float* W_des  = (const float*)d_in[5];  const float* b_des  = (const float*)d_in[6];
    const float* W_num  = (const float*)d_in[7];  const float* b_num  = (const float*)d_in[8];
    const float* W_cat  = (const float*)d_in[9];  const float* b_cat  = (const float*)d_in[10];
    const float* W_in   = (const float*)d_in[11]; const float* b_in   = (const float*)d_in[12];
    const float* s1a_Wl = (const float*)d_in[13]; const float* s1a_bl = (const float*)d_in[14];
    const float* s1a_Wr = (const float*)d_in[15];
    const float* s1b_Wl = (const float*)d_in[16]; const float* s1b_bl = (const float*)d_in[17];
    const float* s1b_Wr = (const float*)d_in[18];
    const float* s2a_Wl = (const float*)d_in[19]; const float* s2a_bl = (const float*)d_in[20];
    const float* s2a_Wr = (const float*)d_in[21];
    const float* s2b_Wl = (const float*)d_in[22]; const float* s2b_bl = (const float*)d_in[23];
    const float* s2b_Wr = (const float*)d_in[24];
    const float* W_o1   = (const float*)d_in[25]; const float* b_o1   = (const float*)d_in[26];
    const float* W_o2   = (const float*)d_in[27]; const float* b_o2   = (const float*)d_in[28];
    float* out = (float*)d_out;

    int N = in_sizes[2] / 4;   // num_prop is [N,4]
    int E = in_sizes[4] / 2;   // edge_index is [2,E]
    const int* srcp = ei;
    const int* dstp = ei + E;

    float *f128, *xA, *tr, *h, *mh, *xB, *ob;
    cudaGetSymbolAddress((void**)&f128, g_f128);
    cudaGetSymbolAddress((void**)&xA, g_xA);
    cudaGetSymbolAddress((void**)&tr, g_tr);
    cudaGetSymbolAddress((void**)&h, g_h);
    cudaGetSymbolAddress((void**)&mh, g_mh);
    cudaGetSymbolAddress((void**)&xB, g_xB);
    cudaGetSymbolAddress((void**)&ob, g_ob);

    cudaFuncSetAttribute(gemm_kernel<1, 1>, cudaFuncAttributeMaxDynamicSharedMemorySize, 100 * 1024);
    cudaFuncSetAttribute(gemm_kernel<4, 0>, cudaFuncAttributeMaxDynamicSharedMemorySize, 72 * 1024);
    cudaFuncSetAttribute(gemm_kernel<4, 1>, cudaFuncAttributeMaxDynamicSharedMemorySize, 72 * 1024);
    cudaFuncSetAttribute(gemm_kernel<4, 2>, cudaFuncAttributeMaxDynamicSharedMemorySize, 72 * 1024);

    int gB = (N + 63) / 64;
    int EB = (E + 255) / 256;
    int NB = (N + 255) / 256;
    int WB = (N * 32 + 255) / 256;
    size_t sm_des = (size_t)(768 * 32 + 32) * 4;
    size_t sm_128 = (size_t)(128 * 128 + 128) * 4;

    // CSR build (incoming edges per dst)
    zero_cnt_kernel<<<NB, 256>>>(N);
    count_kernel<<<EB, 256>>>(dstp, E);
    scan_kernel<<<1, 1024>>>(N);
    scatter_kernel<<<EB, 256>>>(srcp, dstp, E);

    // front features
    front_small_kernel<<<NB, 256>>>(num, cat, W_num, b_num, W_cat, b_cat, N);
    gemm_kernel<1, 1><<<gB, 256, sm_des>>>(des, 768, N, W_des, 768, 32,
                                           nullptr, 0, 0, 0, b_des, f128, 128, 768, 32);
    gemm_kernel<4, 1><<<gB, 256, sm_128>>>(f128, 128, N, W_in, 116, 128,
                                           nullptr, 0, 0, 0, b_in, xA, 128, 128, 128);

    // SAGE block 1
    gemm_kernel<4, 0><<<gB, 256, sm_128>>>(xA, 128, N, s1a_Wl, 128, 64,
                                           s1a_Wr, 128, 64, 1, nullptr, tr, 128, 128, 128);
    agg_a_kernel<<<WB, 256>>>(tr, s1a_bl, h, N);
    agg_b_kernel<<<WB, 256>>>(h, mh, N);
    gemm_kernel<4, 2><<<gB, 256, sm_128>>>(mh, 128, N, s1b_Wl, 64, 128,
                                           s1b_Wr, 64, 128, 0, s1b_bl, xB, 128, 128, 128);

    // SAGE block 2
    gemm_kernel<4, 0><<<gB, 256, sm_128>>>(xB, 128, N, s2a_Wl, 128, 64,
                                           s2a_Wr, 128, 64, 1, nullptr, tr, 128, 128, 128);
    agg_a_kernel<<<WB, 256>>>(tr, s2a_bl, h, N);
    agg_b_kernel<<<WB, 256>>>(h, mh, N);
    gemm_kernel<4, 2><<<gB, 256, sm_128>>>(mh, 128, N, s2b_Wl, 64, 128,
                                           s2b_Wr, 64, 128, 0, s2b_bl, xA, 128, 128, 128);

    // output head
    gemm_kernel<4, 1><<<gB, 256, sm_128>>>(xA, 128, N, W_o1, 128, 128,
                                           nullptr, 0, 0, 0, b_o1, ob, 128, 128, 128);
    out_kernel<<<WB, 256>>>(ob, W_o2, b_o2, out, N);
}

// round 4
// speedup vs baseline: 1.1100x; 1.1100x over previous
#include <cuda_runtime.h>
#include <cuda_bf16.h>
#include <cstdint>

#define GN 50000
#define GE 1600000
#define FULLMASK 0xFFFFFFFFu

typedef unsigned long long u64;

// ---------------- f32x2 packed-FMA helpers (Blackwell FFMA2; only via PTX) ----------------
__device__ __forceinline__ u64 pack2(float lo, float hi) {
    u64 r; asm("mov.b64 %0, {%1, %2};" : "=l"(r) : "f"(lo), "f"(hi)); return r;
}
__device__ __forceinline__ u64 bcast2(float v) {
    u64 r; asm("mov.b64 %0, {%1, %1};" : "=l"(r) : "f"(v)); return r;
}
__device__ __forceinline__ u64 fma2(u64 a, u64 b, u64 c) {
    u64 r; asm("fma.rn.f32x2 %0, %1, %2, %3;" : "=l"(r) : "l"(a), "l"(b), "l"(c)); return r;
}
__device__ __forceinline__ float2 unpack2(u64 v) {
    float2 f; asm("mov.b64 {%0, %1}, %2;" : "=f"(f.x), "=f"(f.y) : "l"(v)); return f;
}

// ---------------- scratch (device globals; no allocation allowed) ----------------
__device__ float g_f128[GN * 128];   // [d | n | c | zeros] per node
__device__ float g_xA[GN * 128];
__device__ float g_tr[GN * 128];     // [t (x@Wl) | r (x@Wr)]
__device__ float g_h[GN * 64];
__device__ float g_mh[GN * 128];     // [mean(h) | h]
__device__ float g_xB[GN * 128];
__device__ float g_ob[GN * 128];
__device__ int   g_cnt[GN];
__device__ int   g_rowptr[GN + 1];
__device__ int   g_cursor[GN];
__device__ int   g_col[GE];
__device__ float g_invdeg[GN];

// ---------------- CSR build ----------------
__global__ void zero_cnt_kernel(int n) {
    int i = blockIdx.x * blockDim.x + threadIdx.x;
    if (i < n) g_cnt[i] = 0;
}

__global__ void count_kernel(const int* __restrict__ dst, int e) {
    int i = blockIdx.x * blockDim.x + threadIdx.x;
    if (i < e) atomicAdd(&g_cnt[dst[i]], 1);
}

// single-block exclusive scan over g_cnt -> g_rowptr, g_cursor, g_invdeg
__global__ void scan_kernel(int n) {
    __shared__ int wsum[32];
    __shared__ int carry_s;
    int tid = threadIdx.x, lane = tid & 31, wid = tid >> 5;
    if (tid == 0) carry_s = 0;
    __syncthreads();
    for (int base = 0; base < n; base += 1024) {
        int i = base + tid;
        int v = (i < n) ? g_cnt[i] : 0;
        int x = v;
        #pragma unroll
        for (int o = 1; o < 32; o <<= 1) {
            int t = __shfl_up_sync(FULLMASK, x, o);
            if (lane >= o) x += t;
        }
        if (lane == 31) wsum[wid] = x;
        __syncthreads();
        if (wid == 0) {
            int y = wsum[lane];
            #pragma unroll
            for (int o = 1; o < 32; o <<= 1) {
                int t = __shfl_up_sync(FULLMASK, y, o);
                if (lane >= o) y += t;
            }
            wsum[lane] = y;
        }
        __syncthreads();
        int incl = x + (wid > 0 ? wsum[wid - 1] : 0);
        int total = wsum[31];
        int carry = carry_s;
        if (i < n) {
            int rp = carry + incl - v;   // exclusive
            g_rowptr[i] = rp;
            g_cursor[i] = rp;
            int d = v > 1 ? v : 1;
            g_invdeg[i] = 1.0f / (float)d;
        }
        __syncthreads();
        if (tid == 0) carry_s = carry + total;
        __syncthreads();
    }
    if (threadIdx.x == 0) g_rowptr[n] = carry_s;
}

__global__ void scatter_kernel(const int* __restrict__ src, const int* __restrict__ dst, int e) {
    int i = blockIdx.x * blockDim.x + threadIdx.x;
    if (i < e) {
        int p = atomicAdd(&g_cursor[dst[i]], 1);
        g_col[p] = src[i];
    }
}

// ---------------- small front features (num 4->42, cat 3->42) ----------------
__global__ void front_small_kernel(const float* __restrict__ num, const float* __restrict__ cat,
                                   const float* __restrict__ Wn, const float* __restrict__ bn,
                                   const float* __restrict__ Wc, const float* __restrict__ bc, int n) {
    int i = blockIdx.x * blockDim.x + threadIdx.x;
    if (i >= n) return;
    float nv0 = num[i * 4 + 0], nv1 = num[i * 4 + 1], nv2 = num[i * 4 + 2], nv3 = num[i * 4 + 3];
    float cv0 = cat[i * 3 + 0], cv1 = cat[i * 3 + 1], cv2 = cat[i * 3 + 2];
    float* f = g_f128 + (size_t)i * 128;
    for (int o = 0; o < 42; o++) {
        float s = bn[o];
        s = fmaf(nv0, Wn[o], s);
        s = fmaf(nv1, Wn[42 + o], s);
        s = fmaf(nv2, Wn[84 + o], s);
        s = fmaf(nv3, Wn[126 + o], s);
        f[32 + o] = s > 0.f ? s : 0.01f * s;
        float s2 = bc[o];
        s2 = fmaf(cv0, Wc[o], s2);
        s2 = fmaf(cv1, Wc[42 + o], s2);
        s2 = fmaf(cv2, Wc[84 + o], s2);
        f[74 + o] = s2 > 0.f ? s2 : 0.01f * s2;
    }
    #pragma unroll
    for (int o = 116; o < 128; o++) f[o] = 0.f;
}

// ---------------- generic GEMM: out[N,C] = act(A[N,K] @ W + bias) ----------------
// W staged once per block in smem, assembled from up to two sources:
//   colcat=1: cols [0,cols0) from W0, cols [cols0,C) from W1
//   colcat=0: rows [0,rows0) from W0, rows [rows0,rows0+rows1) from W1, zeros above
// Block: 256 threads = 8 warps; grid-stride over 64-row tiles; warp = 8 rows.
// CPL=4: lane covers 4 cols as 2 packed f32x2 accumulators (FFMA2 col-pair).
// CPL=1: lane covers 1 col; rows packed in pairs into f32x2 accumulators (FFMA2 row-pair).
// ACT: 0 none, 1 leaky(0.01), 2 relu
template<int CPL, int ACT>
__global__ void __launch_bounds__(256) gemm_kernel(
    const float* __restrict__ A, int lda, int nrows,
    const float* __restrict__ W0, int rows0, int cols0,
    const float* __restrict__ W1, int rows1, int cols1, int colcat,
    const float* __restrict__ bias,
    float* __restrict__ out, int ldo,
    int K, int C)
{
    extern __shared__ float smem[];
    float* Ws = smem;
    float* Bs = smem + K * C;
    int tid = threadIdx.x;
    int total = K * C;
    for (int idx = tid; idx < total; idx += 256) {
        int k = idx / C, c = idx - k * C;
        float v = 0.f;
        if (colcat) {
            v = (c < cols0) ? W0[k * cols0 + c] : W1[k * cols1 + (c - cols0)];
        } else {
            if (k < rows0) v = W0[k * cols0 + c];
            else if (k < rows0 + rows1) v = W1[(k - rows0) * cols1 + c];
        }
        Ws[idx] = v;
    }
    for (int c = tid; c < C; c += 256) Bs[c] = bias ? bias[c] : 0.f;
    __syncthreads();

    const int warp = tid >> 5, lane = tid & 31;
    const int c0 = lane * CPL;

    for (int tile = blockIdx.x * 64; tile < nrows; tile += gridDim.x * 64) {
        const int rowbase = tile + warp * 8;
        const float* Ap[8];
        #pragma unroll
        for (int r = 0; r < 8; r++) {
            int rr = rowbase + r;
            if (rr >= nrows) rr = nrows - 1;
            Ap[r] = A + (size_t)rr * lda;
        }

        if (CPL == 4) {
            u64 acc01[8], acc23[8];
            #pragma unroll
            for (int r = 0; r < 8; r++) { acc01[r] = bcast2(0.f); acc23[r] = bcast2(0.f); }

            for (int k = 0; k < K; k += 4) {
                float4 w0 = *(const float4*)&Ws[(k + 0) * C + c0];
                float4 w1 = *(const float4*)&Ws[(k + 1) * C + c0];
                float4 w2 = *(const float4*)&Ws[(k + 2) * C + c0];
                float4 w3 = *(const float4*)&Ws[(k + 3) * C + c0];
                u64 w0a = pack2(w0.x, w0.y), w0b = pack2(w0.z, w0.w);
                u64 w1a = pack2(w1.x, w1.y), w1b = pack2(w1.z, w1.w);
                u64 w2a = pack2(w2.x, w2.y), w2b = pack2(w2.z, w2.w);
                u64 w3a = pack2(w3.x, w3.y), w3b = pack2(w3.z, w3.w);
                #pragma unroll
                for (int r = 0; r < 8; r++) {
                    float4 a = *(const float4*)(Ap[r] + k);
                    u64 ax = bcast2(a.x);
                    acc01[r] = fma2(ax, w0a, acc01[r]);
                    acc23[r] = fma2(ax, w0b, acc23[r]);
                    u64 ay = bcast2(a.y);
                    acc01[r] = fma2(ay, w1a, acc01[r]);
                    acc23[r] = fma2(ay, w1b, acc23[r]);
                    u64 az = bcast2(a.z);
                    acc01[r] = fma2(az, w2a, acc01[r]);
                    acc23[r] = fma2(az, w2b, acc23[r]);
                    u64 aw = bcast2(a.w);
                    acc01[r] = fma2(aw, w3a, acc01[r]);
                    acc23[r] = fma2(aw, w3b, acc23[r]);
                }
            }

            float b0 = Bs[c0], b1 = Bs[c0 + 1], b2 = Bs[c0 + 2], b3 = Bs[c0 + 3];
            #pragma unroll
            for (int r = 0; r < 8; r++) {
                int rr = rowbase + r;
                if (rr < nrows) {
                    float2 v01 = unpack2(acc01[r]);
                    float2 v23 = unpack2(acc23[r]);
                    float o0 = v01.x + b0, o1 = v01.y + b1, o2 = v23.x + b2, o3 = v23.y + b3;
                    if (ACT == 1) {
                        o0 = o0 > 0.f ? o0 : 0.01f * o0; o1 = o1 > 0.f ? o1 : 0.01f * o1;
                        o2 = o2 > 0.f ? o2 : 0.01f * o2; o3 = o3 > 0.f ? o3 : 0.01f * o3;
                    } else if (ACT == 2) {
                        o0 = o0 > 0.f ? o0 : 0.f; o1 = o1 > 0.f ? o1 : 0.f;
                        o2 = o2 > 0.f ? o2 : 0.f; o3 = o3 > 0.f ? o3 : 0.f;
                    }
                    *(float4*)&out[(size_t)rr * ldo + c0] = make_float4(o0, o1, o2, o3);
                }
            }
        } else {
            // CPL == 1: row-pair packing. acc[p] = (row 2p, row 2p+1) at column c0.
            u64 acc[4];
            #pragma unroll
            for (int p = 0; p < 4; p++) acc[p] = bcast2(0.f);

            for (int k = 0; k < K; k += 4) {
                float w0 = Ws[(k + 0) * C + c0];
                float w1 = Ws[(k + 1) * C + c0];
                float w2 = Ws[(k + 2) * C + c0];
                float w3 = Ws[(k + 3) * C + c0];
                u64 ww0 = bcast2(w0), ww1 = bcast2(w1), ww2 = bcast2(w2), ww3 = bcast2(w3);
                #pragma unroll
                for (int p = 0; p < 4; p++) {
                    float4 a0 = *(const float4*)(Ap[2 * p] + k);
                    float4 a1 = *(const float4*)(Ap[2 * p + 1] + k);
                    acc[p] = fma2(pack2(a0.x, a1.x), ww0, acc[p]);
                    acc[p] = fma2(pack2(a0.y, a1.y), ww1, acc[p]);
                    acc[p] = fma2(pack2(a0.z, a1.z), ww2, acc[p]);
                    acc[p] = fma2(pack2(a0.w, a1.w), ww3, acc[p]);
                }
            }

            float bb = Bs[c0];
            #pragma unroll
            for (int p = 0; p < 4; p++) {
                float2 v = unpack2(acc[p]);
                float o0 = v.x + bb, o1 = v.y + bb;
                if (ACT == 1) {
                    o0 = o0 > 0.f ? o0 : 0.01f * o0; o1 = o1 > 0.f ? o1 : 0.01f * o1;
                } else if (ACT == 2) {
                    o0 = o0 > 0.f ? o0 : 0.f; o1 = o1 > 0.f ? o1 : 0.f;
                }
                int r0 = rowbase + 2 * p, r1 = rowbase + 2 * p + 1;
                if (r0 < nrows) out[(size_t)r0 * ldo + c0] = o0;
                if (r1 < nrows) out[(size_t)r1 * ldo + c0] = o1;
            }
        }
    }
}

// ---------------- aggregation (warp per node, 64 feature cols, 2 per lane) ----------------
// agg_a: h[i] = relu( mean_nbr(t) + bl + r[i] ), t = tr[:,0:64], r = tr[:,64:128]
__global__ void agg_a_kernel(const float* __restrict__ tr, const float* __restrict__ bl,
                             float* __restrict__ h, int n) {
    int w = (blockIdx.x * blockDim.x + threadIdx.x) >> 5;
    if (w >= n) return;
    int lane = threadIdx.x & 31;
    int c = lane * 2;
    int e = g_rowptr[w], end = g_rowptr[w + 1];
    float s0 = 0.f, s1 = 0.f;
    for (; e + 2 <= end; e += 2) {
        int j0 = g_col[e], j1 = g_col[e + 1];
        float2 v0 = *(const float2*)&tr[(size_t)j0 * 128 + c];
        float2 v1 = *(const float2*)&tr[(size_t)j1 * 128 + c];
        s0 += v0.x + v1.x;
        s1 += v0.y + v1.y;
    }
    if (e < end) {
        int j = g_col[e];
        float2 v = *(const float2*)&tr[(size_t)j * 128 + c];
        s0 += v.x; s1 += v.y;
    }
    float id = g_invdeg[w];
    float2 r = *(const float2*)&tr[(size_t)w * 128 + 64 + c];
    float o0 = fmaf(s0, id, bl[c] + r.x);
    float o1 = fmaf(s1, id, bl[c + 1] + r.y);
    o0 = o0 > 0.f ? o0 : 0.f;
    o1 = o1 > 0.f ? o1 : 0.f;
    *(float2*)&h[(size_t)w * 64 + c] = make_float2(o0, o1);
}

// agg_b: mh[i] = [ mean_nbr(h) | h[i] ]
__global__ void agg_b_kernel(const float* __restrict__ h, float* __restrict__ mh, int n) {
    int w = (blockIdx.x * blockDim.x + threadIdx.x) >> 5;
    if (w >= n) return;
    int lane = threadIdx.x & 31;
    int c = lane * 2;
    int e = g_rowptr[w], end = g_rowptr[w + 1];
    float s0 = 0.f, s1 = 0.f;
    for (; e + 2 <= end; e += 2) {
        int j0 = g_col[e], j1 = g_col[e + 1];
        float2 v0 = *(const float2*)&h[(size_t)j0 * 64 + c];
        float2 v1 = *(const float2*)&h[(size_t)j1 * 64 + c];
        s0 += v0.x + v1.x;
        s1 += v0.y + v1.y;
    }
    if (e < end) {
        int j = g_col[e];
        float2 v = *(const float2*)&h[(size_t)j * 64 + c];
        s0 += v.x; s1 += v.y;
    }
    float id = g_invdeg[w];
    float2 hv = *(const float2*)&h[(size_t)w * 64 + c];
    *(float2*)&mh[(size_t)w * 128 + c] = make_float2(s0 * id, s1 * id);
    *(float2*)&mh[(size_t)w * 128 + 64 + c] = hv;
}

// ---------------- final 128->2 projection (warp per node) ----------------
__global__ void out_kernel(const float* __restrict__ ob, const float* __restrict__ W,
                           const float* __restrict__ b, float* __restrict__ out, int n) {
    int w = (blockIdx.x * blockDim.x + threadIdx.x) >> 5;
    if (w >= n) return;
    int lane = threadIdx.x & 31;
    const float* row = ob + (size_t)w * 128;
    float a0 = row[lane];
    float a1 = row[lane + 32];
    float a2 = row[lane + 64];
    float a3 = row[lane + 96];
    float p0 = a0 * W[lane * 2 + 0] + a1 * W[(lane + 32) * 2 + 0]
             + a2 * W[(lane + 64) * 2 + 0] + a3 * W[(lane + 96) * 2 + 0];
    float p1 = a0 * W[lane * 2 + 1] + a1 * W[(lane + 32) * 2 + 1]
             + a2 * W[(lane + 64) * 2 + 1] + a3 * W[(lane + 96) * 2 + 1];
    #pragma unroll
    for (int o = 16; o; o >>= 1) {
        p0 += __shfl_xor_sync(FULLMASK, p0, o);
        p1 += __shfl_xor_sync(FULLMASK, p1, o);
    }
    if (lane == 0) {
        out[(size_t)w * 2 + 0] = p0 + b[0];
        out[(size_t)w * 2 + 1] = p1 + b[1];
    }
}

// ---------------- host launch ----------------
extern "C" void kernel_launch(void* const* d_in, const int* in_sizes, int n_in,
                              void* d_out, int out_size) {
    const float* des    = (const float*)d_in[0];
    const float* num    = (const float*)d_in[2];
    const float* cat    = (const float*)d_in[3];
    const int*   ei     = (const int*)  d_in[4];
    const float* W_des  = (const float*)d_in[5];  const float* b_des  = (const float*)d_in[6];
    const float* W_num  = (const float*)d_in[7];  const float* b_num  = (const float*)d_in[8];
    const float* W_cat  = (const float*)d_in[9];  const float* b_cat  = (const float*)d_in[10];
    const float* W_in   = (const float*)d_in[11]; const float* b_in   = (const float*)d_in[12];
    const float* s1a_Wl = (const float*)d_in[13]; const float* s1a_bl = (const float*)d_in[14];
    const float* s1a_Wr = (const float*)d_in[15];
    const float* s1b_Wl = (const float*)d_in[16]; const float* s1b_bl = (const float*)d_in[17];
    const float* s1b_Wr = (const float*)d_in[18];
    const float* s2a_Wl = (const float*)d_in[19]; const float* s2a_bl = (const float*)d_in[20];
    const float* s2a_Wr = (const float*)d_in[21];
    const float* s2b_Wl = (const float*)d_in[22]; const float* s2b_bl = (const float*)d_in[23];
    const float* s2b_Wr = (const float*)d_in[24];
    const float* W_o1   = (const float*)d_in[25]; const float* b_o1   = (const float*)d_in[26];
    const float* W_o2   = (const float*)d_in[27]; const float* b_o2   = (const float*)d_in[28];
    float* out = (float*)d_out;

    int N = in_sizes[2] / 4;   // num_prop is [N,4]
    int E = in_sizes[4] / 2;   // edge_index is [2,E]
    const int* srcp = ei;
    const int* dstp = ei + E;

    float *f128, *xA, *tr, *h, *mh, *xB, *ob;
    cudaGetSymbolAddress((void**)&f128, g_f128);
    cudaGetSymbolAddress((void**)&xA, g_xA);
    cudaGetSymbolAddress((void**)&tr, g_tr);
    cudaGetSymbolAddress((void**)&h, g_h);
    cudaGetSymbolAddress((void**)&mh, g_mh);
    cudaGetSymbolAddress((void**)&xB, g_xB);
    cudaGetSymbolAddress((void**)&ob, g_ob);

    cudaFuncSetAttribute(gemm_kernel<1, 1>, cudaFuncAttributeMaxDynamicSharedMemorySize, 100 * 1024);
    cudaFuncSetAttribute(gemm_kernel<4, 0>, cudaFuncAttributeMaxDynamicSharedMemorySize, 72 * 1024);
    cudaFuncSetAttribute(gemm_kernel<4, 1>, cudaFuncAttributeMaxDynamicSharedMemorySize, 72 * 1024);
    cudaFuncSetAttribute(gemm_kernel<4, 2>, cudaFuncAttributeMaxDynamicSharedMemorySize, 72 * 1024);

    int rowTiles = (N + 63) / 64;
    int gB  = rowTiles < 444 ? rowTiles : 444;   // 3 CTAs/SM * 148 (65KB smem)
    int gBd = rowTiles < 296 ? rowTiles : 296;   // 2 CTAs/SM * 148 (98KB smem)
    int EB = (E + 255) / 256;
    int NB = (N + 255) / 256;
    int WB = (N * 32 + 255) / 256;
    size_t sm_des = (size_t)(768 * 32 + 32) * 4;
    size_t sm_128 = (size_t)(128 * 128 + 128) * 4;

    // CSR build (incoming edges per dst)
    zero_cnt_kernel<<<NB, 256>>>(N);
    count_kernel<<<EB, 256>>>(dstp, E);
    scan_kernel<<<1, 1024>>>(N);
    scatter_kernel<<<EB, 256>>>(srcp, dstp, E);

    // front features
    front_small_kernel<<<NB, 256>>>(num, cat, W_num, b_num, W_cat, b_cat, N);
    gemm_kernel<1, 1><<<gBd, 256, sm_des>>>(des, 768, N, W_des, 768, 32,
                                            nullptr, 0, 0, 0, b_des, f128, 128, 768, 32);
    gemm_kernel<4, 1><<<gB, 256, sm_128>>>(f128, 128, N, W_in, 116, 128,
                                           nullptr, 0, 0, 0, b_in, xA, 128, 128, 128);

    // SAGE block 1
    gemm_kernel<4, 0><<<gB, 256, sm_128>>>(xA, 128, N, s1a_Wl, 128, 64,
                                           s1a_Wr, 128, 64, 1, nullptr, tr, 128, 128, 128);
    agg_a_kernel<<<WB, 256>>>(tr, s1a_bl, h, N);
    agg_b_kernel<<<WB, 256>>>(h, mh, N);
    gemm_kernel<4, 2><<<gB, 256, sm_128>>>(mh, 128, N, s1b_Wl, 64, 128,
                                           s1b_Wr, 64, 128, 0, s1b_bl, xB, 128, 128, 128);

    // SAGE block 2
    gemm_kernel<4, 0><<<gB, 256, sm_128>>>(xB, 128, N, s2a_Wl, 128, 64,
                                           s2a_Wr, 128, 64, 1, nullptr, tr, 128, 128, 128);
    agg_a_kernel<<<WB, 256>>>(tr, s2a_bl, h, N);
    agg_b_kernel<<<WB, 256>>>(h, mh, N);
    gemm_kernel<4, 2><<<gB, 256, sm_128>>>(mh, 128, N, s2b_Wl, 64, 128,
                                           s2b_Wr, 64, 128, 0, s2b_bl, xA, 128, 128, 128);

    // output head
    gemm_kernel<4, 1><<<gB, 256, sm_128>>>(xA, 128, N, W_o1, 128, 128,
                                           nullptr, 0, 0, 0, b_o1, ob, 128, 128, 128);
    out_kernel<<<WB, 256>>>(ob, W_o2, b_o2, out, N);
}

// round 8
// speedup vs baseline: 1.3897x; 1.2520x over previous
#include <cuda_runtime.h>
#include <cuda_bf16.h>
#include <cstdint>

#define GN 50000
#define GE 1600000
#define FULLMASK 0xFFFFFFFFu

typedef unsigned long long u64;

// ---------------- f32x2 packed-FMA helpers (Blackwell FFMA2; only via PTX) ----------------
__device__ __forceinline__ u64 pack2(float lo, float hi) {
    u64 r; asm("mov.b64 %0, {%1, %2};" : "=l"(r) : "f"(lo), "f"(hi)); return r;
}
__device__ __forceinline__ u64 fma2(u64 a, u64 b, u64 c) {
    u64 r; asm("fma.rn.f32x2 %0, %1, %2, %3;" : "=l"(r) : "l"(a), "l"(b), "l"(c)); return r;
}
__device__ __forceinline__ float2 unpack2(u64 v) {
    float2 f; asm("mov.b64 {%0, %1}, %2;" : "=f"(f.x), "=f"(f.y) : "l"(v)); return f;
}

// ---------------- scratch (device globals; no allocation allowed) ----------------
__device__ float g_f128[GN * 128];   // [d | n | c | zeros] per node
__device__ float g_xA[GN * 128];
__device__ float g_tr[GN * 128];     // [t (x@Wl) | r (x@Wr)]
__device__ float g_h[GN * 64];
__device__ float g_mh[GN * 128];     // [mean(h) | h]
__device__ float g_xB[GN * 128];
__device__ float g_ob[GN * 128];
__device__ int   g_cnt[GN];
__device__ int   g_rowptr[GN + 1];
__device__ int   g_cursor[GN];
__device__ int   g_col[GE];
__device__ float g_invdeg[GN];

// ---------------- CSR build ----------------
__global__ void zero_cnt_kernel(int n) {
    int i = blockIdx.x * blockDim.x + threadIdx.x;
    if (i < n) g_cnt[i] = 0;
}

__global__ void count_kernel(const int* __restrict__ dst, int e) {
    int i = blockIdx.x * blockDim.x + threadIdx.x;
    if (i < e) atomicAdd(&g_cnt[dst[i]], 1);
}

// single-block exclusive scan over g_cnt -> g_rowptr, g_cursor, g_invdeg
__global__ void scan_kernel(int n) {
    __shared__ int wsum[32];
    __shared__ int carry_s;
    int tid = threadIdx.x, lane = tid & 31, wid = tid >> 5;
    if (tid == 0) carry_s = 0;
    __syncthreads();
    for (int base = 0; base < n; base += 1024) {
        int i = base + tid;
        int v = (i < n) ? g_cnt[i] : 0;
        int x = v;
        #pragma unroll
        for (int o = 1; o < 32; o <<= 1) {
            int t = __shfl_up_sync(FULLMASK, x, o);
            if (lane >= o) x += t;
        }
        if (lane == 31) wsum[wid] = x;
        __syncthreads();
        if (wid == 0) {
            int y = wsum[lane];
            #pragma unroll
            for (int o = 1; o < 32; o <<= 1) {
                int t = __shfl_up_sync(FULLMASK, y, o);
                if (lane >= o) y += t;
            }
            wsum[lane] = y;
        }
        __syncthreads();
        int incl = x + (wid > 0 ? wsum[wid - 1] : 0);
        int total = wsum[31];
        int carry = carry_s;
        if (i < n) {
            int rp = carry + incl - v;   // exclusive
            g_rowptr[i] = rp;
            g_cursor[i] = rp;
            int d = v > 1 ? v : 1;
            g_invdeg[i] = 1.0f / (float)d;
        }
        __syncthreads();
        if (tid == 0) carry_s = carry + total;
        __syncthreads();
    }
    if (threadIdx.x == 0) g_rowptr[n] = carry_s;
}

__global__ void scatter_kernel(const int* __restrict__ src, const int* __restrict__ dst, int e) {
    int i = blockIdx.x * blockDim.x + threadIdx.x;
    if (i < e) {
        int p = atomicAdd(&g_cursor[dst[i]], 1);
        g_col[p] = src[i];
    }
}

// ---------------- small front features (num 4->42, cat 3->42) ----------------
__global__ void front_small_kernel(const float* __restrict__ num, const float* __restrict__ cat,
                                   const float* __restrict__ Wn, const float* __restrict__ bn,
                                   const float* __restrict__ Wc, const float* __restrict__ bc, int n) {
    int i = blockIdx.x * blockDim.x + threadIdx.x;
    if (i >= n) return;
    float nv0 = num[i * 4 + 0], nv1 = num[i * 4 + 1], nv2 = num[i * 4 + 2], nv3 = num[i * 4 + 3];
    float cv0 = cat[i * 3 + 0], cv1 = cat[i * 3 + 1], cv2 = cat[i * 3 + 2];
    float* f = g_f128 + (size_t)i * 128;
    for (int o = 0; o < 42; o++) {
        float s = bn[o];
        s = fmaf(nv0, Wn[o], s);
        s = fmaf(nv1, Wn[42 + o], s);
        s = fmaf(nv2, Wn[84 + o], s);
        s = fmaf(nv3, Wn[126 + o], s);
        f[32 + o] = s > 0.f ? s : 0.01f * s;
        float s2 = bc[o];
        s2 = fmaf(cv0, Wc[o], s2);
        s2 = fmaf(cv1, Wc[42 + o], s2);
        s2 = fmaf(cv2, Wc[84 + o], s2);
        f[74 + o] = s2 > 0.f ? s2 : 0.01f * s2;
    }
    #pragma unroll
    for (int o = 116; o < 128; o++) f[o] = 0.f;
}

// ---------------- generic GEMM: out[N,C] = act(A[N,K] @ W + bias) ----------------
// W staged once per block in smem as k-PAIRED u64s: Wp[kp*C+c] = (w[2kp,c], w[2kp+1,c]).
// Accumulators are (even-k partial, odd-k partial) f32x2 — the float4 row load IS two
// k-pairs bitwise (ulonglong2), so the inner loop has ZERO pack instructions.
// Sources assembled from up to two weights:
//   colcat=1: cols [0,cols0) from W0, cols [cols0,C) from W1
//   colcat=0: rows [0,rows0) from W0, rows [rows0,rows0+rows1) from W1, zeros above
// Block: 256 threads = 8 warps; grid-stride over 64-row tiles; warp = 8 rows.
// CPL=4: lane covers 4 cols. CPL=1: lane covers 1 col.
// ACT: 0 none, 1 leaky(0.01), 2 relu
template<int CPL, int ACT>
__global__ void __launch_bounds__(256, 2) gemm_kernel(
    const float* __restrict__ A, int lda, int nrows,
    const float* __restrict__ W0, int rows0, int cols0,
    const float* __restrict__ W1, int rows1, int cols1, int colcat,
    const float* __restrict__ bias,
    float* __restrict__ out, int ldo,
    int K, int C)
{
    extern __shared__ float smem[];
    u64* Wp = (u64*)smem;                       // (K/2) * C pairs
    float* Bs = (float*)(Wp + (K / 2) * C);
    int tid = threadIdx.x;
    int npairs = (K / 2) * C;
    for (int idx = tid; idx < npairs; idx += 256) {
        int kp = idx / C, c = idx - kp * C;
        float v0, v1;
        int k0 = 2 * kp, k1 = 2 * kp + 1;
        if (colcat) {
            v0 = (c < cols0) ? W0[k0 * cols0 + c] : W1[k0 * cols1 + (c - cols0)];
            v1 = (c < cols0) ? W0[k1 * cols0 + c] : W1[k1 * cols1 + (c - cols0)];
        } else {
            v0 = (k0 < rows0) ? W0[k0 * cols0 + c]
               : (k0 < rows0 + rows1) ? W1[(k0 - rows0) * cols1 + c] : 0.f;
            v1 = (k1 < rows0) ? W0[k1 * cols0 + c]
               : (k1 < rows0 + rows1) ? W1[(k1 - rows0) * cols1 + c] : 0.f;
        }
        Wp[idx] = pack2(v0, v1);
    }
    for (int c = tid; c < C; c += 256) Bs[c] = bias ? bias[c] : 0.f;
    __syncthreads();

    const int warp = tid >> 5, lane = tid & 31;
    const int c0 = lane * CPL;
    const int KQ = K / 4;

    for (int tile = blockIdx.x * 64; tile < nrows; tile += gridDim.x * 64) {
        const int rowbase = tile + warp * 8;
        const float* Ap[8];
        #pragma unroll
        for (int r = 0; r < 8; r++) {
            int rr = rowbase + r;
            if (rr >= nrows) rr = nrows - 1;
            Ap[r] = A + (size_t)rr * lda;
        }

        if (CPL == 4) {
            u64 acc[8][4];
            #pragma unroll
            for (int r = 0; r < 8; r++)
                #pragma unroll
                for (int c = 0; c < 4; c++) acc[r][c] = 0ull;

            #pragma unroll 2
            for (int t = 0; t < KQ; t++) {
                const u64* wrow = Wp + (2 * t) * C + c0;
                u64 wA0 = wrow[0], wA1 = wrow[1], wA2 = wrow[2], wA3 = wrow[3];
                u64 wB0 = wrow[C], wB1 = wrow[C + 1], wB2 = wrow[C + 2], wB3 = wrow[C + 3];
                #pragma unroll
                for (int r = 0; r < 8; r++) {
                    ulonglong2 av = *(const ulonglong2*)(Ap[r] + 4 * t);
                    acc[r][0] = fma2(av.x, wA0, acc[r][0]);
                    acc[r][1] = fma2(av.x, wA1, acc[r][1]);
                    acc[r][2] = fma2(av.x, wA2, acc[r][2]);
                    acc[r][3] = fma2(av.x, wA3, acc[r][3]);
                    acc[r][0] = fma2(av.y, wB0, acc[r][0]);
                    acc[r][1] = fma2(av.y, wB1, acc[r][1]);
                    acc[r][2] = fma2(av.y, wB2, acc[r][2]);
                    acc[r][3] = fma2(av.y, wB3, acc[r][3]);
                }
            }

            float b0 = Bs[c0], b1 = Bs[c0 + 1], b2 = Bs[c0 + 2], b3 = Bs[c0 + 3];
            #pragma unroll
            for (int r = 0; r < 8; r++) {
                int rr = rowbase + r;
                if (rr < nrows) {
                    float2 v0 = unpack2(acc[r][0]);
                    float2 v1 = unpack2(acc[r][1]);
                    float2 v2 = unpack2(acc[r][2]);
                    float2 v3 = unpack2(acc[r][3]);
                    float o0 = v0.x + v0.y + b0;
                    float o1 = v1.x + v1.y + b1;
                    float o2 = v2.x + v2.y + b2;
                    float o3 = v3.x + v3.y + b3;
                    if (ACT == 1) {
                        o0 = o0 > 0.f ? o0 : 0.01f * o0; o1 = o1 > 0.f ? o1 : 0.01f * o1;
                        o2 = o2 > 0.f ? o2 : 0.01f * o2; o3 = o3 > 0.f ? o3 : 0.01f * o3;
                    } else if (ACT == 2) {
                        o0 = o0 > 0.f ? o0 : 0.f; o1 = o1 > 0.f ? o1 : 0.f;
                        o2 = o2 > 0.f ? o2 : 0.f; o3 = o3 > 0.f ? o3 : 0.f;
                    }
                    *(float4*)&out[(size_t)rr * ldo + c0] = make_float4(o0, o1, o2, o3);
                }
            }
        } else {
            // CPL == 1: lane covers one col; 8 rows, k-paired accumulators.
            u64 acc[8];
            #pragma unroll
            for (int r = 0; r < 8; r++) acc[r] = 0ull;

            #pragma unroll 2
            for (int t = 0; t < KQ; t++) {
                u64 wA = Wp[(2 * t) * C + c0];
                u64 wB = Wp[(2 * t + 1) * C + c0];
                #pragma unroll
                for (int r = 0; r < 8; r++) {
                    ulonglong2 av = *(const ulonglong2*)(Ap[r] + 4 * t);
                    acc[r] = fma2(av.x, wA, acc[r]);
                    acc[r] = fma2(av.y, wB, acc[r]);
                }
            }

            float bb = Bs[c0];
            #pragma unroll
            for (int r = 0; r < 8; r++) {
                int rr = rowbase + r;
                if (rr < nrows) {
                    float2 v = unpack2(acc[r]);
                    float o = v.x + v.y + bb;
                    if (ACT == 1) o = o > 0.f ? o : 0.01f * o;
                    else if (ACT == 2) o = o > 0.f ? o : 0.f;
                    out[(size_t)rr * ldo + c0] = o;
                }
            }
        }
    }
}

// ---------------- aggregation (warp per node, 64 feature cols, 2 per lane) ----------------
// agg_a: h[i] = relu( mean_nbr(t) + bl + r[i] ), t = tr[:,0:64], r = tr[:,64:128]
__global__ void agg_a_kernel(const float* __restrict__ tr, const float* __restrict__ bl,
                             float* __restrict__ h, int n) {
    int w = (blockIdx.x * blockDim.x + threadIdx.x) >> 5;
    if (w >= n) return;
    int lane = threadIdx.x & 31;
    int c = lane * 2;
    int e = g_rowptr[w], end = g_rowptr[w + 1];
    float s0 = 0.f, s1 = 0.f;
    for (; e + 2 <= end; e += 2) {
        int j0 = g_col[e], j1 = g_col[e + 1];
        float2 v0 = *(const float2*)&tr[(size_t)j0 * 128 + c];
        float2 v1 = *(const float2*)&tr[(size_t)j1 * 128 + c];
        s0 += v0.x + v1.x;
        s1 += v0.y + v1.y;
    }
    if (e < end) {
        int j = g_col[e];
        float2 v = *(const float2*)&tr[(size_t)j * 128 + c];
        s0 += v.x; s1 += v.y;
    }
    float id = g_invdeg[w];
    float2 r = *(const float2*)&tr[(size_t)w * 128 + 64 + c];
    float o0 = fmaf(s0, id, bl[c] + r.x);
    float o1 = fmaf(s1, id, bl[c + 1] + r.y);
    o0 = o0 > 0.f ? o0 : 0.f;
    o1 = o1 > 0.f ? o1 : 0.f;
    *(float2*)&h[(size_t)w * 64 + c] = make_float2(o0, o1);
}

// agg_b: mh[i] = [ mean_nbr(h) | h[i] ]
__global__ void agg_b_kernel(const float* __restrict__ h, float* __restrict__ mh, int n) {
    int w = (blockIdx.x * blockDim.x + threadIdx.x) >> 5;
    if (w >= n) return;
    int lane = threadIdx.x & 31;
    int c = lane * 2;
    int e = g_rowptr[w], end = g_rowptr[w + 1];
    float s0 = 0.f, s1 = 0.f;
    for (; e + 2 <= end; e += 2) {
        int j0 = g_col[e], j1 = g_col[e + 1];
        float2 v0 = *(const float2*)&h[(size_t)j0 * 64 + c];
        float2 v1 = *(const float2*)&h[(size_t)j1 * 64 + c];
        s0 += v0.x + v1.x;
        s1 += v0.y + v1.y;
    }
    if (e < end) {
        int j = g_col[e];
        float2 v = *(const float2*)&h[(size_t)j * 64 + c];
        s0 += v.x; s1 += v.y;
    }
    float id = g_invdeg[w];
    float2 hv = *(const float2*)&h[(size_t)w * 64 + c];
    *(float2*)&mh[(size_t)w * 128 + c] = make_float2(s0 * id, s1 * id);
    *(float2*)&mh[(size_t)w * 128 + 64 + c] = hv;
}

// ---------------- final 128->2 projection (warp per node) ----------------
__global__ void out_kernel(const float* __restrict__ ob, const float* __restrict__ W,
                           const float* __restrict__ b, float* __restrict__ out, int n) {
    int w = (blockIdx.x * blockDim.x + threadIdx.x) >> 5;
    if (w >= n) return;
    int lane = threadIdx.x & 31;
    const float* row = ob + (size_t)w * 128;
    float a0 = row[lane];
    float a1 = row[lane + 32];
    float a2 = row[lane + 64];
    float a3 = row[lane + 96];
    float p0 = a0 * W[lane * 2 + 0] + a1 * W[(lane + 32) * 2 + 0]
             + a2 * W[(lane + 64) * 2 + 0] + a3 * W[(lane + 96) * 2 + 0];
    float p1 = a0 * W[lane * 2 + 1] + a1 * W[(lane + 32) * 2 + 1]
             + a2 * W[(lane + 64) * 2 + 1] + a3 * W[(lane + 96) * 2 + 1];
    #pragma unroll
    for (int o = 16; o; o >>= 1) {
        p0 += __shfl_xor_sync(FULLMASK, p0, o);
        p1 += __shfl_xor_sync(FULLMASK, p1, o);
    }
    if (lane == 0) {
        out[(size_t)w * 2 + 0] = p0 + b[0];
        out[(size_t)w * 2 + 1] = p1 + b[1];
    }
}

// ---------------- host launch ----------------
extern "C" void kernel_launch(void* const* d_in, const int* in_sizes, int n_in,
                              void* d_out, int out_size) {
    const float* des    = (const float*)d_in[0];
    const float* num    = (const float*)d_in[2];
    const float* cat    = (const float*)d_in[3];
    const int*   ei     = (const int*)  d_in[4];
    const float* W_des  = (const float*)d_in[5];  const float* b_des  = (const float*)d_in[6];
    const float* W_num  = (const float*)d_in[7];  const float* b_num  = (const float*)d_in[8];
    const float* W_cat  = (const float*)d_in[9];  const float* b_cat  = (const float*)d_in[10];
    const float* W_in   = (const float*)d_in[11]; const float* b_in   = (const float*)d_in[12];
    const float* s1a_Wl = (const float*)d_in[13]; const float* s1a_bl = (const float*)d_in[14];
    const float* s1a_Wr = (const float*)d_in[15];
    const float* s1b_Wl = (const float*)d_in[16]; const float* s1b_bl = (const float*)d_in[17];
    const float* s1b_Wr = (const float*)d_in[18];
    const float* s2a_Wl = (const float*)d_in[19]; const float* s2a_bl = (const float*)d_in[20];
    const float* s2a_Wr = (const float*)d_in[21];
    const float* s2b_Wl = (const float*)d_in[22]; const float* s2b_bl = (const float*)d_in[23];
    const float* s2b_Wr = (const float*)d_in[24];
    const float* W_o1   = (const float*)d_in[25]; const float* b_o1   = (const float*)d_in[26];
    const float* W_o2   = (const float*)d_in[27]; const float* b_o2   = (const float*)d_in[28];
    float* out = (float*)d_out;

    int N = in_sizes[2] / 4;   // num_prop is [N,4]
    int E = in_sizes[4] / 2;   // edge_index is [2,E]
    const int* srcp = ei;
    const int* dstp = ei + E;

    float *f128, *xA, *tr, *h, *mh, *xB, *ob;
    cudaGetSymbolAddress((void**)&f128, g_f128);
    cudaGetSymbolAddress((void**)&xA, g_xA);
    cudaGetSymbolAddress((void**)&tr, g_tr);
    cudaGetSymbolAddress((void**)&h, g_h);
    cudaGetSymbolAddress((void**)&mh, g_mh);
    cudaGetSymbolAddress((void**)&xB, g_xB);
    cudaGetSymbolAddress((void**)&ob, g_ob);

    cudaFuncSetAttribute(gemm_kernel<1, 1>, cudaFuncAttributeMaxDynamicSharedMemorySize, 100 * 1024);
    cudaFuncSetAttribute(gemm_kernel<4, 0>, cudaFuncAttributeMaxDynamicSharedMemorySize, 72 * 1024);
    cudaFuncSetAttribute(gemm_kernel<4, 1>, cudaFuncAttributeMaxDynamicSharedMemorySize, 72 * 1024);
    cudaFuncSetAttribute(gemm_kernel<4, 2>, cudaFuncAttributeMaxDynamicSharedMemorySize, 72 * 1024);

    int rowTiles = (N + 63) / 64;
    int gB  = rowTiles < 296 ? rowTiles : 296;   // 2 CTAs/SM * 148
    int gBd = rowTiles < 296 ? rowTiles : 296;
    int EB = (E + 255) / 256;
    int NB = (N + 255) / 256;
    int WB = (N * 32 + 255) / 256;
    size_t sm_des = (size_t)(768 * 32 + 32) * 4;
    size_t sm_128 = (size_t)(128 * 128 + 128) * 4;

    // CSR build (incoming edges per dst)
    zero_cnt_kernel<<<NB, 256>>>(N);
    count_kernel<<<EB, 256>>>(dstp, E);
    scan_kernel<<<1, 1024>>>(N);
    scatter_kernel<<<EB, 256>>>(srcp, dstp, E);

    // front features
    front_small_kernel<<<NB, 256>>>(num, cat, W_num, b_num, W_cat, b_cat, N);
    gemm_kernel<1, 1><<<gBd, 256, sm_des>>>(des, 768, N, W_des, 768, 32,
                                            nullptr, 0, 0, 0, b_des, f128, 128, 768, 32);
    gemm_kernel<4, 1><<<gB, 256, sm_128>>>(f128, 128, N, W_in, 116, 128,
                                           nullptr, 0, 0, 0, b_in, xA, 128, 128, 128);

    // SAGE block 1
    gemm_kernel<4, 0><<<gB, 256, sm_128>>>(xA, 128, N, s1a_Wl, 128, 64,
                                           s1a_Wr, 128, 64, 1, nullptr, tr, 128, 128, 128);
    agg_a_kernel<<<WB, 256>>>(tr, s1a_bl, h, N);
    agg_b_kernel<<<WB, 256>>>(h, mh, N);
    gemm_kernel<4, 2><<<gB, 256, sm_128>>>(mh, 128, N, s1b_Wl, 64, 128,
                                           s1b_Wr, 64, 128, 0, s1b_bl, xB, 128, 128, 128);

    // SAGE block 2
    gemm_kernel<4, 0><<<gB, 256, sm_128>>>(xB, 128, N, s2a_Wl, 128, 64,
                                           s2a_Wr, 128, 64, 1, nullptr, tr, 128, 128, 128);
    agg_a_kernel<<<WB, 256>>>(tr, s2a_bl, h, N);
    agg_b_kernel<<<WB, 256>>>(h, mh, N);
    gemm_kernel<4, 2><<<gB, 256, sm_128>>>(mh, 128, N, s2b_Wl, 64, 128,
                                           s2b_Wr, 64, 128, 0, s2b_bl, xA, 128, 128, 128);

    // output head
    gemm_kernel<4, 1><<<gB, 256, sm_128>>>(xA, 128, N, W_o1, 128, 128,
                                           nullptr, 0, 0, 0, b_o1, ob, 128, 128, 128);
    out_kernel<<<WB, 256>>>(ob, W_o2, b_o2, out, N);
}

// round 12
// speedup vs baseline: 1.4451x; 1.0399x over previous
#include <cuda_runtime.h>
#include <cuda_bf16.h>
#include <cstdint>

#define GN 50000
#define GE 1600000
#define FULLMASK 0xFFFFFFFFu

typedef unsigned long long u64;

// ---------------- f32x2 packed-FMA helpers (Blackwell FFMA2; only via PTX) ----------------
__device__ __forceinline__ u64 pack2(float lo, float hi) {
    u64 r; asm("mov.b64 %0, {%1, %2};" : "=l"(r) : "f"(lo), "f"(hi)); return r;
}
__device__ __forceinline__ u64 fma2(u64 a, u64 b, u64 c) {
    u64 r; asm("fma.rn.f32x2 %0, %1, %2, %3;" : "=l"(r) : "l"(a), "l"(b), "l"(c)); return r;
}
__device__ __forceinline__ float2 unpack2(u64 v) {
    float2 f; asm("mov.b64 {%0, %1}, %2;" : "=f"(f.x), "=f"(f.y) : "l"(v)); return f;
}

// ---------------- mma.sync helper (baseline PTX, works on plain sm_103 target) ----------------
__device__ __forceinline__ void mma_bf16(float* c, const uint32_t* a, const uint32_t* b) {
    asm volatile(
        "mma.sync.aligned.m16n8k16.row.col.f32.bf16.bf16.f32 "
        "{%0,%1,%2,%3}, {%4,%5,%6,%7}, {%8,%9}, {%0,%1,%2,%3};\n"
        : "+f"(c[0]), "+f"(c[1]), "+f"(c[2]), "+f"(c[3])
        : "r"(a[0]), "r"(a[1]), "r"(a[2]), "r"(a[3]), "r"(b[0]), "r"(b[1]));
}
__device__ __forceinline__ uint32_t bfpack(__nv_bfloat16 a, __nv_bfloat16 b) {
    __nv_bfloat162 p(a, b);   // a -> low half
    return *(uint32_t*)&p;
}

// ---------------- scratch (device globals; no allocation allowed) ----------------
__device__ float g_f128[GN * 128];   // [d | n | c | zeros] per node
__device__ float g_xA[GN * 128];
__device__ float g_tr[GN * 128];     // [t (x@Wl) | r (x@Wr)]
__device__ float g_h[GN * 64];
__device__ float g_mh[GN * 128];     // [mean(h) | h]
__device__ float g_xB[GN * 128];
__device__ float g_ob[GN * 128];
__device__ int   g_cnt[GN];
__device__ int   g_rowptr[GN + 1];
__device__ int   g_cursor[GN];
__device__ int   g_col[GE];
__device__ float g_invdeg[GN];

// ---------------- CSR build ----------------
__global__ void zero_cnt_kernel(int n) {
    int i = blockIdx.x * blockDim.x + threadIdx.x;
    if (i < n) g_cnt[i] = 0;
}

__global__ void count_kernel(const int* __restrict__ dst, int e) {
    int i = blockIdx.x * blockDim.x + threadIdx.x;
    if (i < e) atomicAdd(&g_cnt[dst[i]], 1);
}

__global__ void scan_kernel(int n) {
    __shared__ int wsum[32];
    __shared__ int carry_s;
    int tid = threadIdx.x, lane = tid & 31, wid = tid >> 5;
    if (tid == 0) carry_s = 0;
    __syncthreads();
    for (int base = 0; base < n; base += 1024) {
        int i = base + tid;
        int v = (i < n) ? g_cnt[i] : 0;
        int x = v;
        #pragma unroll
        for (int o = 1; o < 32; o <<= 1) {
            int t = __shfl_up_sync(FULLMASK, x, o);
            if (lane >= o) x += t;
        }
        if (lane == 31) wsum[wid] = x;
        __syncthreads();
        if (wid == 0) {
            int y = wsum[lane];
            #pragma unroll
            for (int o = 1; o < 32; o <<= 1) {
                int t = __shfl_up_sync(FULLMASK, y, o);
                if (lane >= o) y += t;
            }
            wsum[lane] = y;
        }
        __syncthreads();
        int incl = x + (wid > 0 ? wsum[wid - 1] : 0);
        int total = wsum[31];
        int carry = carry_s;
        if (i < n) {
            int rp = carry + incl - v;
            g_rowptr[i] = rp;
            g_cursor[i] = rp;
            int d = v > 1 ? v : 1;
            g_invdeg[i] = 1.0f / (float)d;
        }
        __syncthreads();
        if (tid == 0) carry_s = carry + total;
        __syncthreads();
    }
    if (threadIdx.x == 0) g_rowptr[n] = carry_s;
}

__global__ void scatter_kernel(const int* __restrict__ src, const int* __restrict__ dst, int e) {
    int i = blockIdx.x * blockDim.x + threadIdx.x;
    if (i < e) {
        int p = atomicAdd(&g_cursor[dst[i]], 1);
        g_col[p] = src[i];
    }
}

// ---------------- small front features (num 4->42, cat 3->42) ----------------
__global__ void front_small_kernel(const float* __restrict__ num, const float* __restrict__ cat,
                                   const float* __restrict__ Wn, const float* __restrict__ bn,
                                   const float* __restrict__ Wc, const float* __restrict__ bc, int n) {
    int i = blockIdx.x * blockDim.x + threadIdx.x;
    if (i >= n) return;
    float nv0 = num[i * 4 + 0], nv1 = num[i * 4 + 1], nv2 = num[i * 4 + 2], nv3 = num[i * 4 + 3];
    float cv0 = cat[i * 3 + 0], cv1 = cat[i * 3 + 1], cv2 = cat[i * 3 + 2];
    float* f = g_f128 + (size_t)i * 128;
    for (int o = 0; o < 42; o++) {
        float s = bn[o];
        s = fmaf(nv0, Wn[o], s);
        s = fmaf(nv1, Wn[42 + o], s);
        s = fmaf(nv2, Wn[84 + o], s);
        s = fmaf(nv3, Wn[126 + o], s);
        f[32 + o] = s > 0.f ? s : 0.01f * s;
        float s2 = bc[o];
        s2 = fmaf(cv0, Wc[o], s2);
        s2 = fmaf(cv1, Wc[42 + o], s2);
        s2 = fmaf(cv2, Wc[84 + o], s2);
        f[74 + o] = s2 > 0.f ? s2 : 0.01f * s2;
    }
    #pragma unroll
    for (int o = 116; o < 128; o++) f[o] = 0.f;
}

// ---------------- FFMA2 GEMM (kept for des 768->32): k-pair packed ----------------
template<int CPL, int ACT>
__global__ void __launch_bounds__(256, 2) gemm_kernel(
    const float* __restrict__ A, int lda, int nrows,
    const float* __restrict__ W0, int rows0, int cols0,
    const float* __restrict__ W1, int rows1, int cols1, int colcat,
    const float* __restrict__ bias,
    float* __restrict__ out, int ldo,
    int K, int C)
{
    extern __shared__ char smem[];
    u64* Wp = (u64*)smem;
    float* Bs = (float*)(Wp + (K / 2) * C);
    int tid = threadIdx.x;
    int npairs = (K / 2) * C;
    for (int idx = tid; idx < npairs; idx += 256) {
        int kp = idx / C, c = idx - kp * C;
        float v0, v1;
        int k0 = 2 * kp, k1 = 2 * kp + 1;
        if (colcat) {
            v0 = (c < cols0) ? W0[k0 * cols0 + c] : W1[k0 * cols1 + (c - cols0)];
            v1 = (c < cols0) ? W0[k1 * cols0 + c] : W1[k1 * cols1 + (c - cols0)];
        } else {
            v0 = (k0 < rows0) ? W0[k0 * cols0 + c]
               : (k0 < rows0 + rows1) ? W1[(k0 - rows0) * cols1 + c] : 0.f;
            v1 = (k1 < rows0) ? W0[k1 * cols0 + c]
               : (k1 < rows0 + rows1) ? W1[(k1 - rows0) * cols1 + c] : 0.f;
        }
        Wp[idx] = pack2(v0, v1);
    }
    for (int c = tid; c < C; c += 256) Bs[c] = bias ? bias[c] : 0.f;
    __syncthreads();

    const int warp = tid >> 5, lane = tid & 31;
    const int c0 = lane * CPL;
    const int KQ = K / 4;

    for (int tile = blockIdx.x * 64; tile < nrows; tile += gridDim.x * 64) {
        const int rowbase = tile + warp * 8;
        const float* Ap[8];
        #pragma unroll
        for (int r = 0; r < 8; r++) {
            int rr = rowbase + r;
            if (rr >= nrows) rr = nrows - 1;
            Ap[r] = A + (size_t)rr * lda;
        }
        u64 acc[8];
        #pragma unroll
        for (int r = 0; r < 8; r++) acc[r] = 0ull;

        #pragma unroll 2
        for (int t = 0; t < KQ; t++) {
            u64 wA = Wp[(2 * t) * C + c0];
            u64 wB = Wp[(2 * t + 1) * C + c0];
            #pragma unroll
            for (int r = 0; r < 8; r++) {
                ulonglong2 av = *(const ulonglong2*)(Ap[r] + 4 * t);
                acc[r] = fma2(av.x, wA, acc[r]);
                acc[r] = fma2(av.y, wB, acc[r]);
            }
        }

        float bb = Bs[c0];
        #pragma unroll
        for (int r = 0; r < 8; r++) {
            int rr = rowbase + r;
            if (rr < nrows) {
                float2 v = unpack2(acc[r]);
                float o = v.x + v.y + bb;
                if (ACT == 1) o = o > 0.f ? o : 0.01f * o;
                else if (ACT == 2) o = o > 0.f ? o : 0.f;
                out[(size_t)rr * ldo + c0] = o;
            }
        }
    }
}

// ---------------- mma.sync tensor GEMM: out[N,128] = act(A[N,128] @ W[128,128] + b) --------
// Split-bf16: x = hi + lo; D = Ahi*Bhi + Ahi*Blo + Alo*Bhi (fp32 accumulators).
// Smem: A and W as [row][k] bf16, row stride 272B (68 b32; 68 mod 32 = 4 -> all fragment
// loads bank-conflict-free).
// Warp = 16 rows x 128 cols = 16 m16n8 accumulator tiles; K = 8 ksteps of 16.
#define RSTRIDE 272
#define MMA_AHI  0
#define MMA_ALO  34816
#define MMA_BHI  69632
#define MMA_BLO  104448
#define MMA_BIAS 139264
#define MMA_TOT  139776

template<int ACT>
__global__ void __launch_bounds__(256, 1) mma_gemm_kernel(
    const float* __restrict__ A, int lda, int nrows,
    const float* __restrict__ W0, int rows0, int cols0,
    const float* __restrict__ W1, int cols1, int colcat,
    const float* __restrict__ bias,
    float* __restrict__ out, int ldo)
{
    extern __shared__ char smem[];
    const int tid = threadIdx.x;
    const int wid = tid >> 5, lane = tid & 31;
    const int g = lane >> 2, t = lane & 3;

    // bias
    float* Bsf = (float*)(smem + MMA_BIAS);
    for (int c = tid; c < 128; c += 256) Bsf[c] = bias ? bias[c] : 0.f;

    // stage weights once per CTA: Ws[n][k] hi/lo bf16 (B operand, col-major = [n][k])
    // NOTE: colcat=0 with rows0<128 and W1==nullptr pads k>=rows0 with zeros (W_in case).
    for (int idx = tid; idx < 128 * 128; idx += 256) {
        int k = idx >> 7, n = idx & 127;
        float v;
        if (colcat) v = (n < cols0) ? W0[k * cols0 + n] : W1[k * cols1 + (n - cols0)];
        else        v = (k < rows0) ? W0[k * 128 + n]
                      : (W1 ? W1[(k - rows0) * 128 + n] : 0.f);
        __nv_bfloat16 hi = __float2bfloat16(v);
        __nv_bfloat16 lo = __float2bfloat16(v - __bfloat162float(hi));
        int off = n * RSTRIDE + k * 2;
        *(__nv_bfloat16*)(smem + MMA_BHI + off) = hi;
        *(__nv_bfloat16*)(smem + MMA_BLO + off) = lo;
    }

    for (int tile = blockIdx.x * 128; tile < nrows; tile += gridDim.x * 128) {
        // stage A tile hi/lo: As[r][k]
        for (int idx = tid; idx < 128 * 32; idx += 256) {
            int r = idx >> 5, k4 = (idx & 31) * 4;
            int rr = tile + r; if (rr >= nrows) rr = nrows - 1;
            float4 v = *(const float4*)(A + (size_t)rr * lda + k4);
            __nv_bfloat16 h0 = __float2bfloat16(v.x), h1 = __float2bfloat16(v.y);
            __nv_bfloat16 h2 = __float2bfloat16(v.z), h3 = __float2bfloat16(v.w);
            __nv_bfloat16 l0 = __float2bfloat16(v.x - __bfloat162float(h0));
            __nv_bfloat16 l1 = __float2bfloat16(v.y - __bfloat162float(h1));
            __nv_bfloat16 l2 = __float2bfloat16(v.z - __bfloat162float(h2));
            __nv_bfloat16 l3 = __float2bfloat16(v.w - __bfloat162float(h3));
            uint2 hp; hp.x = bfpack(h0, h1); hp.y = bfpack(h2, h3);
            uint2 lp; lp.x = bfpack(l0, l1); lp.y = bfpack(l2, l3);
            int off = r * RSTRIDE + k4 * 2;
            *(uint2*)(smem + MMA_AHI + off) = hp;
            *(uint2*)(smem + MMA_ALO + off) = lp;
        }
        __syncthreads();

        float acc[16][4];
        #pragma unroll
        for (int nt = 0; nt < 16; nt++)
            #pragma unroll
            for (int j = 0; j < 4; j++) acc[nt][j] = 0.f;

        const int wbase = wid * 16;
        #pragma unroll
        for (int ks = 0; ks < 8; ks++) {
            int ro0 = (wbase + g) * RSTRIDE;
            int ro1 = (wbase + g + 8) * RSTRIDE;
            int co0 = (8 * ks + t) * 4;
            int co1 = co0 + 16;
            uint32_t ah[4], al[4];
            ah[0] = *(uint32_t*)(smem + MMA_AHI + ro0 + co0);
            ah[1] = *(uint32_t*)(smem + MMA_AHI + ro1 + co0);
            ah[2] = *(uint32_t*)(smem + MMA_AHI + ro0 + co1);
            ah[3] = *(uint32_t*)(smem + MMA_AHI + ro1 + co1);
            al[0] = *(uint32_t*)(smem + MMA_ALO + ro0 + co0);
            al[1] = *(uint32_t*)(smem + MMA_ALO + ro1 + co0);
            al[2] = *(uint32_t*)(smem + MMA_ALO + ro0 + co1);
            al[3] = *(uint32_t*)(smem + MMA_ALO + ro1 + co1);
            #pragma unroll
            for (int nt = 0; nt < 16; nt++) {
                int bro = (nt * 8 + g) * RSTRIDE;
                uint32_t bh[2], bl[2];
                bh[0] = *(uint32_t*)(smem + MMA_BHI + bro + co0);
                bh[1] = *(uint32_t*)(smem + MMA_BHI + bro + co1);
                bl[0] = *(uint32_t*)(smem + MMA_BLO + bro + co0);
                bl[1] = *(uint32_t*)(smem + MMA_BLO + bro + co1);
                mma_bf16(acc[nt], ah, bh);
                mma_bf16(acc[nt], ah, bl);
                mma_bf16(acc[nt], al, bh);
            }
        }

        // epilogue: D frag c0,c1 = rows wbase+g cols 2t,2t+1; c2,c3 = row +8
        int r0 = tile + wbase + g;
        int r1 = r0 + 8;
        #pragma unroll
        for (int nt = 0; nt < 16; nt++) {
            int cc = nt * 8 + t * 2;
            float o0 = acc[nt][0] + Bsf[cc], o1 = acc[nt][1] + Bsf[cc + 1];
            float o2 = acc[nt][2] + Bsf[cc], o3 = acc[nt][3] + Bsf[cc + 1];
            if (ACT == 1) {
                o0 = o0 > 0.f ? o0 : 0.01f * o0; o1 = o1 > 0.f ? o1 : 0.01f * o1;
                o2 = o2 > 0.f ? o2 : 0.01f * o2; o3 = o3 > 0.f ? o3 : 0.01f * o3;
            } else if (ACT == 2) {
                o0 = o0 > 0.f ? o0 : 0.f; o1 = o1 > 0.f ? o1 : 0.f;
                o2 = o2 > 0.f ? o2 : 0.f; o3 = o3 > 0.f ? o3 : 0.f;
            }
            if (r0 < nrows) *(float2*)(out + (size_t)r0 * ldo + cc) = make_float2(o0, o1);
            if (r1 < nrows) *(float2*)(out + (size_t)r1 * ldo + cc) = make_float2(o2, o3);
        }
        __syncthreads();   // A buffers reused next tile
    }
}

// ---------------- aggregation (warp per node, 64 feature cols, 2 per lane) ----------------
__global__ void agg_a_kernel(const float* __restrict__ tr, const float* __restrict__ bl,
                             float* __restrict__ h, int n) {
    int w = (blockIdx.x * blockDim.x + threadIdx.x) >> 5;
    if (w >= n) return;
    int lane = threadIdx.x & 31;
    int c = lane * 2;
    int e = g_rowptr[w], end = g_rowptr[w + 1];
    float s0 = 0.f, s1 = 0.f;
    for (; e + 2 <= end; e += 2) {
        int j0 = g_col[e], j1 = g_col[e + 1];
        float2 v0 = *(const float2*)&tr[(size_t)j0 * 128 + c];
        float2 v1 = *(const float2*)&tr[(size_t)j1 * 128 + c];
        s0 += v0.x + v1.x;
        s1 += v0.y + v1.y;
    }
    if (e < end) {
        int j = g_col[e];
        float2 v = *(const float2*)&tr[(size_t)j * 128 + c];
        s0 += v.x; s1 += v.y;
    }
    float id = g_invdeg[w];
    float2 r = *(const float2*)&tr[(size_t)w * 128 + 64 + c];
    float o0 = fmaf(s0, id, bl[c] + r.x);
    float o1 = fmaf(s1, id, bl[c + 1] + r.y);
    o0 = o0 > 0.f ? o0 : 0.f;
    o1 = o1 > 0.f ? o1 : 0.f;
    *(float2*)&h[(size_t)w * 64 + c] = make_float2(o0, o1);
}

__global__ void agg_b_kernel(const float* __restrict__ h, float* __restrict__ mh, int n) {
    int w = (blockIdx.x * blockDim.x + threadIdx.x) >> 5;
    if (w >= n) return;
    int lane = threadIdx.x & 31;
    int c = lane * 2;
    int e = g_rowptr[w], end = g_rowptr[w + 1];
    float s0 = 0.f, s1 = 0.f;
    for (; e + 2 <= end; e += 2) {
        int j0 = g_col[e], j1 = g_col[e + 1];
        float2 v0 = *(const float2*)&h[(size_t)j0 * 64 + c];
        float2 v1 = *(const float2*)&h[(size_t)j1 * 64 + c];
        s0 += v0.x + v1.x;
        s1 += v0.y + v1.y;
    }
    if (e < end) {
        int j = g_col[e];
        float2 v = *(const float2*)&h[(size_t)j * 64 + c];
        s0 += v.x; s1 += v.y;
    }
    float id = g_invdeg[w];
    float2 hv = *(const float2*)&h[(size_t)w * 64 + c];
    *(float2*)&mh[(size_t)w * 128 + c] = make_float2(s0 * id, s1 * id);
    *(float2*)&mh[(size_t)w * 128 + 64 + c] = hv;
}

// ---------------- final 128->2 projection (warp per node) ----------------
__global__ void out_kernel(const float* __restrict__ ob, const float* __restrict__ W,
                           const float* __restrict__ b, float* __restrict__ out, int n) {
    int w = (blockIdx.x * blockDim.x + threadIdx.x) >> 5;
    if (w >= n) return;
    int lane = threadIdx.x & 31;
    const float* row = ob + (size_t)w * 128;
    float a0 = row[lane];
    float a1 = row[lane + 32];
    float a2 = row[lane + 64];
    float a3 = row[lane + 96];
    float p0 = a0 * W[lane * 2 + 0] + a1 * W[(lane + 32) * 2 + 0]
             + a2 * W[(lane + 64) * 2 + 0] + a3 * W[(lane + 96) * 2 + 0];
    float p1 = a0 * W[lane * 2 + 1] + a1 * W[(lane + 32) * 2 + 1]
             + a2 * W[(lane + 64) * 2 + 1] + a3 * W[(lane + 96) * 2 + 1];
    #pragma unroll
    for (int o = 16; o; o >>= 1) {
        p0 += __shfl_xor_sync(FULLMASK, p0, o);
        p1 += __shfl_xor_sync(FULLMASK, p1, o);
    }
    if (lane == 0) {
        out[(size_t)w * 2 + 0] = p0 + b[0];
        out[(size_t)w * 2 + 1] = p1 + b[1];
    }
}

// ---------------- host launch ----------------
extern "C" void kernel_launch(void* const* d_in, const int* in_sizes, int n_in,
                              void* d_out, int out_size) {
    const float* des    = (const float*)d_in[0];
    const float* num    = (const float*)d_in[2];
    const float* cat    = (const float*)d_in[3];
    const int*   ei     = (const int*)  d_in[4];
    const float* W_des  = (const float*)d_in[5];  const float* b_des  = (const float*)d_in[6];
    const float* W_num  = (const float*)d_in[7];  const float* b_num  = (const float*)d_in[8];
    const float* W_cat  = (const float*)d_in[9];  const float* b_cat  = (const float*)d_in[10];
    const float* W_in   = (const float*)d_in[11]; const float* b_in   = (const float*)d_in[12];
    const float* s1a_Wl = (const float*)d_in[13]; const float* s1a_bl = (const float*)d_in[14];
    const float* s1a_Wr = (const float*)d_in[15];
    const float* s1b_Wl = (const float*)d_in[16]; const float* s1b_bl = (const float*)d_in[17];
    const float* s1b_Wr = (const float*)d_in[18];
    const float* s2a_Wl = (const float*)d_in[19]; const float* s2a_bl = (const float*)d_in[20];
    const float* s2a_Wr = (const float*)d_in[21];
    const float* s2b_Wl = (const float*)d_in[22]; const float* s2b_bl = (const float*)d_in[23];
    const float* s2b_Wr = (const float*)d_in[24];
    const float* W_o1   = (const float*)d_in[25]; const float* b_o1   = (const float*)d_in[26];
    const float* W_o2   = (const float*)d_in[27]; const float* b_o2   = (const float*)d_in[28];
    float* out = (float*)d_out;

    int N = in_sizes[2] / 4;   // num_prop is [N,4]
    int E = in_sizes[4] / 2;   // edge_index is [2,E]
    const int* srcp = ei;
    const int* dstp = ei + E;

    float *f128, *xA, *tr, *h, *mh, *xB, *ob;
    cudaGetSymbolAddress((void**)&f128, g_f128);
    cudaGetSymbolAddress((void**)&xA, g_xA);
    cudaGetSymbolAddress((void**)&tr, g_tr);
    cudaGetSymbolAddress((void**)&h, g_h);
    cudaGetSymbolAddress((void**)&mh, g_mh);
    cudaGetSymbolAddress((void**)&xB, g_xB);
    cudaGetSymbolAddress((void**)&ob, g_ob);

    cudaFuncSetAttribute(gemm_kernel<1, 1>, cudaFuncAttributeMaxDynamicSharedMemorySize, 100 * 1024);
    cudaFuncSetAttribute(mma_gemm_kernel<0>, cudaFuncAttributeMaxDynamicSharedMemorySize, MMA_TOT);
    cudaFuncSetAttribute(mma_gemm_kernel<1>, cudaFuncAttributeMaxDynamicSharedMemorySize, MMA_TOT);
    cudaFuncSetAttribute(mma_gemm_kernel<2>, cudaFuncAttributeMaxDynamicSharedMemorySize, MMA_TOT);

    int rowTiles64 = (N + 63) / 64;
    int gBd = rowTiles64 < 296 ? rowTiles64 : 296;
    int tcTiles = (N + 127) / 128;
    int gTC = tcTiles < 148 ? tcTiles : 148;
    int EB = (E + 255) / 256;
    int NB = (N + 255) / 256;
    int WB = (N * 32 + 255) / 256;
    size_t sm_des = (size_t)(768 * 32 + 32) * 4;

    // CSR build (incoming edges per dst)
    zero_cnt_kernel<<<NB, 256>>>(N);
    count_kernel<<<EB, 256>>>(dstp, E);
    scan_kernel<<<1, 1024>>>(N);
    scatter_kernel<<<EB, 256>>>(srcp, dstp, E);

    // front features
    front_small_kernel<<<NB, 256>>>(num, cat, W_num, b_num, W_cat, b_cat, N);
    gemm_kernel<1, 1><<<gBd, 256, sm_des>>>(des, 768, N, W_des, 768, 32,
                                            nullptr, 0, 0, 0, b_des, f128, 128, 768, 32);
    mma_gemm_kernel<1><<<gTC, 256, MMA_TOT>>>(f128, 128, N, W_in, 116, 128,
                                              nullptr, 0, 0, b_in, xA, 128);

    // SAGE block 1
    mma_gemm_kernel<0><<<gTC, 256, MMA_TOT>>>(xA, 128, N, s1a_Wl, 128, 64,
                                              s1a_Wr, 64, 1, nullptr, tr, 128);
    agg_a_kernel<<<WB, 256>>>(tr, s1a_bl, h, N);
    agg_b_kernel<<<WB, 256>>>(h, mh, N);
    mma_gemm_kernel<2><<<gTC, 256, MMA_TOT>>>(mh, 128, N, s1b_Wl, 64, 128,
                                              s1b_Wr, 128, 0, s1b_bl, xB, 128);

    // SAGE block 2
    mma_gemm_kernel<0><<<gTC, 256, MMA_TOT>>>(xB, 128, N, s2a_Wl, 128, 64,
                                              s2a_Wr, 64, 1, nullptr, tr, 128);
    agg_a_kernel<<<WB, 256>>>(tr, s2a_bl, h, N);
    agg_b_kernel<<<WB, 256>>>(h, mh, N);
    mma_gemm_kernel<2><<<gTC, 256, MMA_TOT>>>(mh, 128, N, s2b_Wl, 64, 128,
                                              s2b_Wr, 128, 0, s2b_bl, xA, 128);

    // output head
    mma_gemm_kernel<1><<<gTC, 256, MMA_TOT>>>(xA, 128, N, W_o1, 128, 128,
                                              nullptr, 0, 0, b_o1, ob, 128);
    out_kernel<<<WB, 256>>>(ob, W_o2, b_o2, out, N);
}

// round 13
// speedup vs baseline: 2.2454x; 1.5537x over previous
#include <cuda_runtime.h>
#include <cuda_bf16.h>
#include <cstdint>

#define GN 50000
#define GE 1600000
#define FULLMASK 0xFFFFFFFFu

typedef unsigned long long u64;

// ---------------- f32x2 packed-FMA helpers (Blackwell FFMA2; only via PTX) ----------------
__device__ __forceinline__ u64 pack2(float lo, float hi) {
    u64 r; asm("mov.b64 %0, {%1, %2};" : "=l"(r) : "f"(lo), "f"(hi)); return r;
}
__device__ __forceinline__ u64 fma2(u64 a, u64 b, u64 c) {
    u64 r; asm("fma.rn.f32x2 %0, %1, %2, %3;" : "=l"(r) : "l"(a), "l"(b), "l"(c)); return r;
}
__device__ __forceinline__ float2 unpack2(u64 v) {
    float2 f; asm("mov.b64 {%0, %1}, %2;" : "=f"(f.x), "=f"(f.y) : "l"(v)); return f;
}

// ---------------- mma.sync + ldmatrix helpers (baseline PTX, plain sm_103 target) ----------
__device__ __forceinline__ void mma_bf16(float* c, const uint32_t* a, const uint32_t* b) {
    asm volatile(
        "mma.sync.aligned.m16n8k16.row.col.f32.bf16.bf16.f32 "
        "{%0,%1,%2,%3}, {%4,%5,%6,%7}, {%8,%9}, {%0,%1,%2,%3};\n"
        : "+f"(c[0]), "+f"(c[1]), "+f"(c[2]), "+f"(c[3])
        : "r"(a[0]), "r"(a[1]), "r"(a[2]), "r"(a[3]), "r"(b[0]), "r"(b[1]));
}
__device__ __forceinline__ void ldsm_x4(uint32_t* r, uint32_t addr) {
    asm volatile("ldmatrix.sync.aligned.m8n8.x4.shared.b16 {%0,%1,%2,%3}, [%4];"
                 : "=r"(r[0]), "=r"(r[1]), "=r"(r[2]), "=r"(r[3]) : "r"(addr));
}
__device__ __forceinline__ uint32_t smem_u32(const void* p) {
    uint32_t a;
    asm("{ .reg .u64 t; cvta.to.shared.u64 t, %1; cvt.u32.u64 %0, t; }" : "=r"(a) : "l"(p));
    return a;
}
__device__ __forceinline__ uint32_t bfpack(__nv_bfloat16 a, __nv_bfloat16 b) {
    __nv_bfloat162 p(a, b);
    return *(uint32_t*)&p;
}

// ---------------- scratch (device globals; no allocation allowed) ----------------
__device__ float g_f128[GN * 128];
__device__ float g_xA[GN * 128];
__device__ float g_tr[GN * 128];
__device__ float g_h[GN * 64];
__device__ float g_mh[GN * 128];
__device__ float g_xB[GN * 128];
__device__ float g_ob[GN * 128];
__device__ int   g_cnt[GN];
__device__ int   g_rowptr[GN + 1];
__device__ int   g_cursor[GN];
__device__ int   g_col[GE];
__device__ float g_invdeg[GN];

// ---------------- CSR build ----------------
__global__ void zero_cnt_kernel(int n) {
    int i = blockIdx.x * blockDim.x + threadIdx.x;
    if (i < n) g_cnt[i] = 0;
}

__global__ void count_kernel(const int* __restrict__ dst, int e) {
    int i = blockIdx.x * blockDim.x + threadIdx.x;
    if (i < e) atomicAdd(&g_cnt[dst[i]], 1);
}

__global__ void scan_kernel(int n) {
    __shared__ int wsum[32];
    __shared__ int carry_s;
    int tid = threadIdx.x, lane = tid & 31, wid = tid >> 5;
    if (tid == 0) carry_s = 0;
    __syncthreads();
    for (int base = 0; base < n; base += 1024) {
        int i = base + tid;
        int v = (i < n) ? g_cnt[i] : 0;
        int x = v;
        #pragma unroll
        for (int o = 1; o < 32; o <<= 1) {
            int t = __shfl_up_sync(FULLMASK, x, o);
            if (lane >= o) x += t;
        }
        if (lane == 31) wsum[wid] = x;
        __syncthreads();
        if (wid == 0) {
            int y = wsum[lane];
            #pragma unroll
            for (int o = 1; o < 32; o <<= 1) {
                int t = __shfl_up_sync(FULLMASK, y, o);
                if (lane >= o) y += t;
            }
            wsum[lane] = y;
        }
        __syncthreads();
        int incl = x + (wid > 0 ? wsum[wid - 1] : 0);
        int total = wsum[31];
        int carry = carry_s;
        if (i < n) {
            int rp = carry + incl - v;
            g_rowptr[i] = rp;
            g_cursor[i] = rp;
            int d = v > 1 ? v : 1;
            g_invdeg[i] = 1.0f / (float)d;
        }
        __syncthreads();
        if (tid == 0) carry_s = carry + total;
        __syncthreads();
    }
    if (threadIdx.x == 0) g_rowptr[n] = carry_s;
}

__global__ void scatter_kernel(const int* __restrict__ src, const int* __restrict__ dst, int e) {
    int i = blockIdx.x * blockDim.x + threadIdx.x;
    if (i < e) {
        int p = atomicAdd(&g_cursor[dst[i]], 1);
        g_col[p] = src[i];
    }
}

// ---------------- small front features (num 4->42, cat 3->42) ----------------
__global__ void front_small_kernel(const float* __restrict__ num, const float* __restrict__ cat,
                                   const float* __restrict__ Wn, const float* __restrict__ bn,
                                   const float* __restrict__ Wc, const float* __restrict__ bc, int n) {
    int i = blockIdx.x * blockDim.x + threadIdx.x;
    if (i >= n) return;
    float nv0 = num[i * 4 + 0], nv1 = num[i * 4 + 1], nv2 = num[i * 4 + 2], nv3 = num[i * 4 + 3];
    float cv0 = cat[i * 3 + 0], cv1 = cat[i * 3 + 1], cv2 = cat[i * 3 + 2];
    float* f = g_f128 + (size_t)i * 128;
    for (int o = 0; o < 42; o++) {
        float s = bn[o];
        s = fmaf(nv0, Wn[o], s);
        s = fmaf(nv1, Wn[42 + o], s);
        s = fmaf(nv2, Wn[84 + o], s);
        s = fmaf(nv3, Wn[126 + o], s);
        f[32 + o] = s > 0.f ? s : 0.01f * s;
        float s2 = bc[o];
        s2 = fmaf(cv0, Wc[o], s2);
        s2 = fmaf(cv1, Wc[42 + o], s2);
        s2 = fmaf(cv2, Wc[84 + o], s2);
        f[74 + o] = s2 > 0.f ? s2 : 0.01f * s2;
    }
    #pragma unroll
    for (int o = 116; o < 128; o++) f[o] = 0.f;
}

// ---------------- FFMA2 GEMM (kept for des 768->32): k-pair packed ----------------
template<int CPL, int ACT>
__global__ void __launch_bounds__(256, 2) gemm_kernel(
    const float* __restrict__ A, int lda, int nrows,
    const float* __restrict__ W0, int rows0, int cols0,
    const float* __restrict__ W1, int rows1, int cols1, int colcat,
    const float* __restrict__ bias,
    float* __restrict__ out, int ldo,
    int K, int C)
{
    extern __shared__ char smem[];
    u64* Wp = (u64*)smem;
    float* Bs = (float*)(Wp + (K / 2) * C);
    int tid = threadIdx.x;
    int npairs = (K / 2) * C;
    for (int idx = tid; idx < npairs; idx += 256) {
        int kp = idx / C, c = idx - kp * C;
        float v0, v1;
        int k0 = 2 * kp, k1 = 2 * kp + 1;
        if (colcat) {
            v0 = (c < cols0) ? W0[k0 * cols0 + c] : W1[k0 * cols1 + (c - cols0)];
            v1 = (c < cols0) ? W0[k1 * cols0 + c] : W1[k1 * cols1 + (c - cols0)];
        } else {
            v0 = (k0 < rows0) ? W0[k0 * cols0 + c]
               : (k0 < rows0 + rows1) ? W1[(k0 - rows0) * cols1 + c] : 0.f;
            v1 = (k1 < rows0) ? W0[k1 * cols0 + c]
               : (k1 < rows0 + rows1) ? W1[(k1 - rows0) * cols1 + c] : 0.f;
        }
        Wp[idx] = pack2(v0, v1);
    }
    for (int c = tid; c < C; c += 256) Bs[c] = bias ? bias[c] : 0.f;
    __syncthreads();

    const int warp = tid >> 5, lane = tid & 31;
    const int c0 = lane * CPL;
    const int KQ = K / 4;

    for (int tile = blockIdx.x * 64; tile < nrows; tile += gridDim.x * 64) {
        const int rowbase = tile + warp * 8;
        const float* Ap[8];
        #pragma unroll
        for (int r = 0; r < 8; r++) {
            int rr = rowbase + r;
            if (rr >= nrows) rr = nrows - 1;
            Ap[r] = A + (size_t)rr * lda;
        }
        u64 acc[8];
        #pragma unroll
        for (int r = 0; r < 8; r++) acc[r] = 0ull;

        #pragma unroll 2
        for (int t = 0; t < KQ; t++) {
            u64 wA = Wp[(2 * t) * C + c0];
            u64 wB = Wp[(2 * t + 1) * C + c0];
            #pragma unroll
            for (int r = 0; r < 8; r++) {
                ulonglong2 av = *(const ulonglong2*)(Ap[r] + 4 * t);
                acc[r] = fma2(av.x, wA, acc[r]);
                acc[r] = fma2(av.y, wB, acc[r]);
            }
        }

        float bb = Bs[c0];
        #pragma unroll
        for (int r = 0; r < 8; r++) {
            int rr = rowbase + r;
            if (rr < nrows) {
                float2 v = unpack2(acc[r]);
                float o = v.x + v.y + bb;
                if (ACT == 1) o = o > 0.f ? o : 0.01f * o;
                else if (ACT == 2) o = o > 0.f ? o : 0.f;
                out[(size_t)rr * ldo + c0] = o;
            }
        }
    }
}

// ---------------- mma.sync tensor GEMM v2: 512 thr, ldmatrix, split columns -------------
// Split-bf16: D = Ahi*Bhi + Ahi*Blo + Alo*Bhi (fp32 accum).
// Smem map (same as R12): A/B hi/lo [row][k] bf16, RSTRIDE=272 B (conflict-free).
// 16 warps: warp = 16 rows x 64 cols -> rowblk = (wid>>1)*16, colblk = (wid&1)*64, 8 nt.
// A frags: 1 ldmatrix.x4 per region per kstep. B frags hi+lo: ONE x4 per nt per kstep
// (tile0=Bhi@k0, tile1=Bhi@k8, tile2=Blo@k0, tile3=Blo@k8 via per-lane-group addresses).
#define RSTRIDE 272
#define MMA_AHI  0
#define MMA_ALO  34816
#define MMA_BHI  69632
#define MMA_BLO  104448
#define MMA_BIAS 139264
#define MMA_TOT  139776

template<int ACT>
__global__ void __launch_bounds__(512, 1) mma_gemm_kernel(
    const float* __restrict__ A, int lda, int nrows,
    const float* __restrict__ W0, int rows0, int cols0,
    const float* __restrict__ W1, int cols1, int colcat,
    const float* __restrict__ bias,
    float* __restrict__ out, int ldo)
{
    extern __shared__ char smem[];
    const uint32_t sbase = smem_u32(smem);
    const int tid = threadIdx.x;
    const int wid = tid >> 5, lane = tid & 31;
    const int g = lane >> 2, t = lane & 3;
    const int rowblk = (wid >> 1) * 16;
    const int colblk = (wid & 1) * 64;

    // per-thread ldmatrix base offsets
    // A: lanes 0-7 rows 0-7@k0 | 8-15 rows 8-15@k0 | 16-23 rows 0-7@k8 | 24-31 rows 8-15@k8
    const uint32_t a_thr = (uint32_t)((rowblk + (lane & 15)) * RSTRIDE + ((lane >> 4) * 8) * 2);
    // B: lanes 0-7 Bhi rows@k0 | 8-15 Bhi rows@k8 | 16-23 Blo rows@k0 | 24-31 Blo rows@k8
    const uint32_t b_thr = (uint32_t)((lane < 16 ? MMA_BHI : MMA_BLO)
                                      + (lane & 7) * RSTRIDE + (((lane >> 3) & 1) * 8) * 2);

    // bias
    float* Bsf = (float*)(smem + MMA_BIAS);
    for (int c = tid; c < 128; c += 512) Bsf[c] = bias ? bias[c] : 0.f;

    // stage weights once per CTA: Ws[n][k] hi/lo bf16
    for (int idx = tid; idx < 128 * 128; idx += 512) {
        int k = idx >> 7, n = idx & 127;
        float v;
        if (colcat) v = (n < cols0) ? W0[k * cols0 + n] : W1[k * cols1 + (n - cols0)];
        else        v = (k < rows0) ? W0[k * 128 + n]
                      : (W1 ? W1[(k - rows0) * 128 + n] : 0.f);
        __nv_bfloat16 hi = __float2bfloat16(v);
        __nv_bfloat16 lo = __float2bfloat16(v - __bfloat162float(hi));
        int off = n * RSTRIDE + k * 2;
        *(__nv_bfloat16*)(smem + MMA_BHI + off) = hi;
        *(__nv_bfloat16*)(smem + MMA_BLO + off) = lo;
    }

    for (int tile = blockIdx.x * 128; tile < nrows; tile += gridDim.x * 128) {
        // stage A tile hi/lo: As[r][k]
        for (int idx = tid; idx < 128 * 32; idx += 512) {
            int r = idx >> 5, k4 = (idx & 31) * 4;
            int rr = tile + r; if (rr >= nrows) rr = nrows - 1;
            float4 v = *(const float4*)(A + (size_t)rr * lda + k4);
            __nv_bfloat16 h0 = __float2bfloat16(v.x), h1 = __float2bfloat16(v.y);
            __nv_bfloat16 h2 = __float2bfloat16(v.z), h3 = __float2bfloat16(v.w);
            __nv_bfloat16 l0 = __float2bfloat16(v.x - __bfloat162float(h0));
            __nv_bfloat16 l1 = __float2bfloat16(v.y - __bfloat162float(h1));
            __nv_bfloat16 l2 = __float2bfloat16(v.z - __bfloat162float(h2));
            __nv_bfloat16 l3 = __float2bfloat16(v.w - __bfloat162float(h3));
            uint2 hp; hp.x = bfpack(h0, h1); hp.y = bfpack(h2, h3);
            uint2 lp; lp.x = bfpack(l0, l1); lp.y = bfpack(l2, l3);
            int off = r * RSTRIDE + k4 * 2;
            *(uint2*)(smem + MMA_AHI + off) = hp;
            *(uint2*)(smem + MMA_ALO + off) = lp;
        }
        __syncthreads();

        float acc[8][4];
        #pragma unroll
        for (int nt = 0; nt < 8; nt++)
            #pragma unroll
            for (int j = 0; j < 4; j++) acc[nt][j] = 0.f;

        #pragma unroll
        for (int ks = 0; ks < 8; ks++) {
            uint32_t koff = (uint32_t)(32 * ks);
            uint32_t ah[4], al[4];
            ldsm_x4(ah, sbase + MMA_AHI + a_thr + koff);
            ldsm_x4(al, sbase + MMA_ALO + a_thr + koff);
            #pragma unroll
            for (int nt = 0; nt < 8; nt++) {
                uint32_t bf[4];
                ldsm_x4(bf, sbase + b_thr + (uint32_t)((colblk + nt * 8) * RSTRIDE) + koff);
                mma_bf16(acc[nt], ah, bf);          // Ahi*Bhi  (bf[0],bf[1])
                mma_bf16(acc[nt], ah, bf + 2);      // Ahi*Blo  (bf[2],bf[3])
                mma_bf16(acc[nt], al, bf);          // Alo*Bhi
            }
        }

        // epilogue: rows rowblk+g / +8, cols colblk + nt*8 + 2t
        int r0 = tile + rowblk + g;
        int r1 = r0 + 8;
        #pragma unroll
        for (int nt = 0; nt < 8; nt++) {
            int cc = colblk + nt * 8 + t * 2;
            float o0 = acc[nt][0] + Bsf[cc], o1 = acc[nt][1] + Bsf[cc + 1];
            float o2 = acc[nt][2] + Bsf[cc], o3 = acc[nt][3] + Bsf[cc + 1];
            if (ACT == 1) {
                o0 = o0 > 0.f ? o0 : 0.01f * o0; o1 = o1 > 0.f ? o1 : 0.01f * o1;
                o2 = o2 > 0.f ? o2 : 0.01f * o2; o3 = o3 > 0.f ? o3 : 0.01f * o3;
            } else if (ACT == 2) {
                o0 = o0 > 0.f ? o0 : 0.f; o1 = o1 > 0.f ? o1 : 0.f;
                o2 = o2 > 0.f ? o2 : 0.f; o3 = o3 > 0.f ? o3 : 0.f;
            }
            if (r0 < nrows) *(float2*)(out + (size_t)r0 * ldo + cc) = make_float2(o0, o1);
            if (r1 < nrows) *(float2*)(out + (size_t)r1 * ldo + cc) = make_float2(o2, o3);
        }
        __syncthreads();
    }
}

// ---------------- aggregation (warp per node, 64 feature cols, 2 per lane) ----------------
__global__ void agg_a_kernel(const float* __restrict__ tr, const float* __restrict__ bl,
                             float* __restrict__ h, int n) {
    int w = (blockIdx.x * blockDim.x + threadIdx.x) >> 5;
    if (w >= n) return;
    int lane = threadIdx.x & 31;
    int c = lane * 2;
    int e = g_rowptr[w], end = g_rowptr[w + 1];
    float s0 = 0.f, s1 = 0.f;
    for (; e + 2 <= end; e += 2) {
        int j0 = g_col[e], j1 = g_col[e + 1];
        float2 v0 = *(const float2*)&tr[(size_t)j0 * 128 + c];
        float2 v1 = *(const float2*)&tr[(size_t)j1 * 128 + c];
        s0 += v0.x + v1.x;
        s1 += v0.y + v1.y;
    }
    if (e < end) {
        int j = g_col[e];
        float2 v = *(const float2*)&tr[(size_t)j * 128 + c];
        s0 += v.x; s1 += v.y;
    }
    float id = g_invdeg[w];
    float2 r = *(const float2*)&tr[(size_t)w * 128 + 64 + c];
    float o0 = fmaf(s0, id, bl[c] + r.x);
    float o1 = fmaf(s1, id, bl[c + 1] + r.y);
    o0 = o0 > 0.f ? o0 : 0.f;
    o1 = o1 > 0.f ? o1 : 0.f;
    *(float2*)&h[(size_t)w * 64 + c] = make_float2(o0, o1);
}

__global__ void agg_b_kernel(const float* __restrict__ h, float* __restrict__ mh, int n) {
    int w = (blockIdx.x * blockDim.x + threadIdx.x) >> 5;
    if (w >= n) return;
    int lane = threadIdx.x & 31;
    int c = lane * 2;
    int e = g_rowptr[w], end = g_rowptr[w + 1];
    float s0 = 0.f, s1 = 0.f;
    for (; e + 2 <= end; e += 2) {
        int j0 = g_col[e], j1 = g_col[e + 1];
        float2 v0 = *(const float2*)&h[(size_t)j0 * 64 + c];
        float2 v1 = *(const float2*)&h[(size_t)j1 * 64 + c];
        s0 += v0.x + v1.x;
        s1 += v0.y + v1.y;
    }
    if (e < end) {
        int j = g_col[e];
        float2 v = *(const float2*)&h[(size_t)j * 64 + c];
        s0 += v.x; s1 += v.y;
    }
    float id = g_invdeg[w];
    float2 hv = *(const float2*)&h[(size_t)w * 64 + c];
    *(float2*)&mh[(size_t)w * 128 + c] = make_float2(s0 * id, s1 * id);
    *(float2*)&mh[(size_t)w * 128 + 64 + c] = hv;
}

// ---------------- final 128->2 projection (warp per node) ----------------
__global__ void out_kernel(const float* __restrict__ ob, const float* __restrict__ W,
                           const float* __restrict__ b, float* __restrict__ out, int n) {
    int w = (blockIdx.x * blockDim.x + threadIdx.x) >> 5;
    if (w >= n) return;
    int lane = threadIdx.x & 31;
    const float* row = ob + (size_t)w * 128;
    float a0 = row[lane];
    float a1 = row[lane + 32];
    float a2 = row[lane + 64];
    float a3 = row[lane + 96];
    float p0 = a0 * W[lane * 2 + 0] + a1 * W[(lane + 32) * 2 + 0]
             + a2 * W[(lane + 64) * 2 + 0] + a3 * W[(lane + 96) * 2 + 0];
    float p1 = a0 * W[lane * 2 + 1] + a1 * W[(lane + 32) * 2 + 1]
             + a2 * W[(lane + 64) * 2 + 1] + a3 * W[(lane + 96) * 2 + 1];
    #pragma unroll
    for (int o = 16; o; o >>= 1) {
        p0 += __shfl_xor_sync(FULLMASK, p0, o);
        p1 += __shfl_xor_sync(FULLMASK, p1, o);
    }
    if (lane == 0) {
        out[(size_t)w * 2 + 0] = p0 + b[0];
        out[(size_t)w * 2 + 1] = p1 + b[1];
    }
}

// ---------------- host launch ----------------
extern "C" void kernel_launch(void* const* d_in, const int* in_sizes, int n_in,
                              void* d_out, int out_size) {
    const float* des    = (const float*)d_in[0];
    const float* num    = (const float*)d_in[2];
    const float* cat    = (const float*)d_in[3];
    const int*   ei     = (const int*)  d_in[4];
    const float* W_des  = (const float*)d_in[5];  const float* b_des  = (const float*)d_in[6];
    const float* W_num  = (const float*)d_in[7];  const float* b_num  = (const float*)d_in[8];
    const float* W_cat  = (const float*)d_in[9];  const float* b_cat  = (const float*)d_in[10];
    const float* W_in   = (const float*)d_in[11]; const float* b_in   = (const float*)d_in[12];
    const float* s1a_Wl = (const float*)d_in[13]; const float* s1a_bl = (const float*)d_in[14];
    const float* s1a_Wr = (const float*)d_in[15];
    const float* s1b_Wl = (const float*)d_in[16]; const float* s1b_bl = (const float*)d_in[17];
    const float* s1b_Wr = (const float*)d_in[18];
    const float* s2a_Wl = (const float*)d_in[19]; const float* s2a_bl = (const float*)d_in[20];
    const float* s2a_Wr = (const float*)d_in[21];
    const float* s2b_Wl = (const float*)d_in[22]; const float* s2b_bl = (const float*)d_in[23];
    const float* s2b_Wr = (const float*)d_in[24];
    const float* W_o1   = (const float*)d_in[25]; const float* b_o1   = (const float*)d_in[26];
    const float* W_o2   = (const float*)d_in[27]; const float* b_o2   = (const float*)d_in[28];
    float* out = (float*)d_out;

    int N = in_sizes[2] / 4;   // num_prop is [N,4]
    int E = in_sizes[4] / 2;   // edge_index is [2,E]
    const int* srcp = ei;
    const int* dstp = ei + E;

    float *f128, *xA, *tr, *h, *mh, *xB, *ob;
    cudaGetSymbolAddress((void**)&f128, g_f128);
    cudaGetSymbolAddress((void**)&xA, g_xA);
    cudaGetSymbolAddress((void**)&tr, g_tr);
    cudaGetSymbolAddress((void**)&h, g_h);
    cudaGetSymbolAddress((void**)&mh, g_mh);
    cudaGetSymbolAddress((void**)&xB, g_xB);
    cudaGetSymbolAddress((void**)&ob, g_ob);

    cudaFuncSetAttribute(gemm_kernel<1, 1>, cudaFuncAttributeMaxDynamicSharedMemorySize, 100 * 1024);
    cudaFuncSetAttribute(mma_gemm_kernel<0>, cudaFuncAttributeMaxDynamicSharedMemorySize, MMA_TOT);
    cudaFuncSetAttribute(mma_gemm_kernel<1>, cudaFuncAttributeMaxDynamicSharedMemorySize, MMA_TOT);
    cudaFuncSetAttribute(mma_gemm_kernel<2>, cudaFuncAttributeMaxDynamicSharedMemorySize, MMA_TOT);

    int rowTiles64 = (N + 63) / 64;
    int gBd = rowTiles64 < 296 ? rowTiles64 : 296;
    int tcTiles = (N + 127) / 128;
    int gTC = tcTiles < 148 ? tcTiles : 148;
    int EB = (E + 255) / 256;
    int NB = (N + 255) / 256;
    int WB = (N * 32 + 255) / 256;
    size_t sm_des = (size_t)(768 * 32 + 32) * 4;

    // CSR build (incoming edges per dst)
    zero_cnt_kernel<<<NB, 256>>>(N);
    count_kernel<<<EB, 256>>>(dstp, E);
    scan_kernel<<<1, 1024>>>(N);
    scatter_kernel<<<EB, 256>>>(srcp, dstp, E);

    // front features
    front_small_kernel<<<NB, 256>>>(num, cat, W_num, b_num, W_cat, b_cat, N);
    gemm_kernel<1, 1><<<gBd, 256, sm_des>>>(des, 768, N, W_des, 768, 32,
                                            nullptr, 0, 0, 0, b_des, f128, 128, 768, 32);
    mma_gemm_kernel<1><<<gTC, 512, MMA_TOT>>>(f128, 128, N, W_in, 116, 128,
                                              nullptr, 0, 0, b_in, xA, 128);

    // SAGE block 1
    mma_gemm_kernel<0><<<gTC, 512, MMA_TOT>>>(xA, 128, N, s1a_Wl, 128, 64,
                                              s1a_Wr, 64, 1, nullptr, tr, 128);
    agg_a_kernel<<<WB, 256>>>(tr, s1a_bl, h, N);
    agg_b_kernel<<<WB, 256>>>(h, mh, N);
    mma_gemm_kernel<2><<<gTC, 512, MMA_TOT>>>(mh, 128, N, s1b_Wl, 64, 128,
                                              s1b_Wr, 128, 0, s1b_bl, xB, 128);

    // SAGE block 2
    mma_gemm_kernel<0><<<gTC, 512, MMA_TOT>>>(xB, 128, N, s2a_Wl, 128, 64,
                                              s2a_Wr, 64, 1, nullptr, tr, 128);
    agg_a_kernel<<<WB, 256>>>(tr, s2a_bl, h, N);
    agg_b_kernel<<<WB, 256>>>(h, mh, N);
    mma_gemm_kernel<2><<<gTC, 512, MMA_TOT>>>(mh, 128, N, s2b_Wl, 64, 128,
                                              s2b_Wr, 128, 0, s2b_bl, xA, 128);

    // output head
    mma_gemm_kernel<1><<<gTC, 512, MMA_TOT>>>(xA, 128, N, W_o1, 128, 128,
                                              nullptr, 0, 0, b_o1, ob, 128);
    out_kernel<<<WB, 256>>>(ob, W_o2, b_o2, out, N);
}